// round 5
// baseline (speedup 1.0000x reference)
#include <cuda_runtime.h>
#include <stdint.h>

#define BB 2
#define TT 2048
#define CC 1024
#define HH 16
#define DD 64

// Scratch (allocation-free rule: __device__ globals)
__device__ float g_q[BB * HH * TT * DD];
__device__ float g_k[BB * HH * TT * DD];
__device__ float g_v[BB * HH * TT * DD];
__device__ float g_ao[BB * TT * CC];
// Cached unnormalized softmax numerators e = exp(s - m_running), per (b,h,t,s)
__device__ float g_e[(size_t)BB * HH * TT * TT];
// Regrow bitmask: 64 words of 32 bits per (bh, t) row
__device__ uint32_t g_mask[(size_t)BB * HH * TT * (TT / 32)];

// ---------------------------------------------------------------------------
// Threefry-2x32, key = (0, 42)  (== jax.random.key(42))
// ---------------------------------------------------------------------------
__device__ __forceinline__ uint2 threefry_0_42(uint32_t x0, uint32_t x1) {
    const uint32_t ks0 = 0u;
    const uint32_t ks1 = 42u;
    const uint32_t ks2 = 0x1BD11BDAu ^ ks0 ^ ks1;
    x0 += ks0; x1 += ks1;
#define TF_RND(rot) { x0 += x1; x1 = __funnelshift_l(x1, x1, (rot)); x1 ^= x0; }
    TF_RND(13) TF_RND(15) TF_RND(26) TF_RND(6)
    x0 += ks1; x1 += ks2 + 1u;
    TF_RND(17) TF_RND(29) TF_RND(16) TF_RND(24)
    x0 += ks2; x1 += ks0 + 2u;
    TF_RND(13) TF_RND(15) TF_RND(26) TF_RND(6)
    x0 += ks0; x1 += ks1 + 3u;
    TF_RND(17) TF_RND(29) TF_RND(16) TF_RND(24)
    x0 += ks1; x1 += ks2 + 4u;
    TF_RND(13) TF_RND(15) TF_RND(26) TF_RND(6)
    x0 += ks2; x1 += ks0 + 5u;
#undef TF_RND
    return make_uint2(x0, x1);
}

__device__ __forceinline__ bool regrow_test(uint32_t idx) {
    uint2 rb = threefry_0_42(0u, idx);
    uint32_t bits = rb.x ^ rb.y;
    return (bits >> 9) <= 419430u;
}

// ---------------------------------------------------------------------------
// Regrow mask precompute (input-independent). One warp per 32-bit word.
// ---------------------------------------------------------------------------
__global__ void __launch_bounds__(256)
mask_kernel() {
    const int t  = blockIdx.y;
    const int bh = blockIdx.z;
    const int w  = blockIdx.x * 8 + (threadIdx.x >> 5);
    if (w * 32 > t) return;
    const int lane = threadIdx.x & 31;
    const uint32_t s = (uint32_t)(w * 32 + lane);
    const uint32_t idx = ((uint32_t)(bh * TT + t)) * (uint32_t)TT + s;
    uint32_t word = __ballot_sync(0xffffffffu, regrow_test(idx));
    if (lane == 0) g_mask[((size_t)(bh * TT + t)) * (TT / 32) + w] = word;
}

// ---------------------------------------------------------------------------
// GEMM: C[M,N] = A[M,K] @ B[K,N] + bias[N], register-prefetch double buffer.
// mode 0: row-major store into Cout (A from g_ao); mode 1: QKV scatter.
// BM=BN=128, BK=16, 256 threads, 8x8 micro.
// ---------------------------------------------------------------------------
__global__ void __launch_bounds__(256)
gemm_kernel(const float* __restrict__ A_in, const float* __restrict__ Bmat,
            const float* __restrict__ bias, float* __restrict__ Cout,
            int M, int N, int K, int mode) {
    __shared__ float As[16][132];
    __shared__ float Bs[16][132];

    const float* A = (mode == 1) ? A_in : (const float*)g_ao;

    int tid = threadIdx.x;
    int tx = tid & 15, ty = tid >> 4;
    int m0 = blockIdx.y * 128, n0 = blockIdx.x * 128;

    float acc[8][8];
#pragma unroll
    for (int i = 0; i < 8; i++)
#pragma unroll
        for (int j = 0; j < 8; j++) acc[i][j] = 0.f;

    // A-load mapping: e = tid + rep*256; r=e>>2, c4=e&3
    // B-load mapping: e = tid + rep*256; r=e>>5, c4=e&31
    float4 pa[2], pb[2];
#pragma unroll
    for (int rep = 0; rep < 2; rep++) {
        int e = tid + rep * 256;
        pa[rep] = *(const float4*)&A[(size_t)(m0 + (e >> 2)) * K + (e & 3) * 4];
        pb[rep] = *(const float4*)&Bmat[(size_t)(e >> 5) * N + n0 + (e & 31) * 4];
    }

    for (int k0 = 0; k0 < K; k0 += 16) {
#pragma unroll
        for (int rep = 0; rep < 2; rep++) {
            int e = tid + rep * 256;
            int r = e >> 2, c4 = e & 3;
            As[c4 * 4 + 0][r] = pa[rep].x;
            As[c4 * 4 + 1][r] = pa[rep].y;
            As[c4 * 4 + 2][r] = pa[rep].z;
            As[c4 * 4 + 3][r] = pa[rep].w;
            *(float4*)&Bs[e >> 5][(e & 31) * 4] = pb[rep];
        }
        __syncthreads();

        if (k0 + 16 < K) {
#pragma unroll
            for (int rep = 0; rep < 2; rep++) {
                int e = tid + rep * 256;
                pa[rep] = *(const float4*)
                    &A[(size_t)(m0 + (e >> 2)) * K + k0 + 16 + (e & 3) * 4];
                pb[rep] = *(const float4*)
                    &Bmat[(size_t)(k0 + 16 + (e >> 5)) * N + n0 + (e & 31) * 4];
            }
        }

#pragma unroll
        for (int kk = 0; kk < 16; kk++) {
            float a[8], b[8];
            *(float4*)&a[0] = *(const float4*)&As[kk][ty * 4];
            *(float4*)&a[4] = *(const float4*)&As[kk][64 + ty * 4];
            *(float4*)&b[0] = *(const float4*)&Bs[kk][tx * 4];
            *(float4*)&b[4] = *(const float4*)&Bs[kk][64 + tx * 4];
#pragma unroll
            for (int i = 0; i < 8; i++)
#pragma unroll
                for (int j = 0; j < 8; j++) acc[i][j] += a[i] * b[j];
        }
        __syncthreads();
    }

#pragma unroll
    for (int i = 0; i < 8; i++) {
        int m = m0 + ((i < 4) ? (ty * 4 + i) : (64 + ty * 4 + (i - 4)));
#pragma unroll
        for (int jg = 0; jg < 2; jg++) {
            int n = n0 + tx * 4 + jg * 64;
            float4 val;
            val.x = acc[i][jg * 4 + 0] + bias[n + 0];
            val.y = acc[i][jg * 4 + 1] + bias[n + 1];
            val.z = acc[i][jg * 4 + 2] + bias[n + 2];
            val.w = acc[i][jg * 4 + 3] + bias[n + 3];
            if (mode == 0) {
                *(float4*)&Cout[(size_t)m * N + n] = val;
            } else {
                int part = n >> 10;
                int rem = n & 1023;
                int h = rem >> 6;
                int d = rem & 63;
                int b = m >> 11;
                int t = m & 2047;
                float* dst = (part == 0) ? g_q : (part == 1) ? g_k : g_v;
                *(float4*)&dst[((((size_t)b * HH) + h) * TT + t) * DD + d] = val;
            }
        }
    }
}

// ---------------------------------------------------------------------------
// Attention: 128 q-rows/block, 64-key tiles, 256 threads, 8x4 micro-tile.
//   ty = tid>>4 -> rows ty*8..+7 ; tx = tid&15 -> cols tx*4..+3
// Pass 1: QK, online max/sum, cache e=exp(s-m_run) to gmem, tile max in smem.
// Pass 2: p = e * exp(m_it - m_fin)/l, keep = p>0.01 || maskbit, AV.
// Register-prefetched K/V tiles. smem 103424 B -> 2 blocks/SM.
// ---------------------------------------------------------------------------
__global__ void __launch_bounds__(256)
attn_kernel() {
    extern __shared__ float smem[];
    float (*q_sm)[68]  = (float(*)[68])(smem);                    // 128x68
    float (*kv_sm)[68] = (float(*)[68])(smem + 128 * 68);         // 64x68
    float (*a_sm)[68]  = (float(*)[68])(smem + 192 * 68);         // 128x68
    float (*mh)[32]    = (float(*)[32])(smem + 320 * 68);         // 128x32

    const int bh = blockIdx.z * HH + blockIdx.y;
    const int qb = (int)(gridDim.x - 1 - blockIdx.x);  // heavy blocks first
    const int t0 = qb * 128;
    const int tid = threadIdx.x;
    const int ty = tid >> 4;
    const int tx = tid & 15;

    const float* qbase = g_q + ((size_t)bh * TT) * DD;
    const float* kbase = g_k + ((size_t)bh * TT) * DD;
    const float* vbase = g_v + ((size_t)bh * TT) * DD;

    // Load Q tile: 128 rows x 16 float4, 8 per thread
#pragma unroll
    for (int rep = 0; rep < 8; rep++) {
        int e = tid + rep * 256;
        int rr = e >> 4, c4 = e & 15;
        *(float4*)&q_sm[rr][c4 * 4] =
            *(const float4*)&qbase[(size_t)(t0 + rr) * DD + c4 * 4];
    }

    const int ntiles = 2 * qb + 2;
    float m[8], l[8];
#pragma unroll
    for (int i = 0; i < 8; i++) { m[i] = -1e30f; l[i] = 0.f; }

    // Prefetch K tile 0 (64 rows x 16 float4, 4/thread)
    float4 pf[4];
    const int prr = tid >> 4, pc4 = tid & 15;  // element base for rep stride 16 rows
#pragma unroll
    for (int rep = 0; rep < 4; rep++)
        pf[rep] = *(const float4*)&kbase[(size_t)(prr + rep * 16) * DD + pc4 * 4];

    // ---------------- Pass 1: QK, online max/sum, cache e ----------------
    for (int it = 0; it < ntiles; it++) {
        const int s0 = it * 64;
#pragma unroll
        for (int rep = 0; rep < 4; rep++)
            *(float4*)&kv_sm[prr + rep * 16][pc4 * 4] = pf[rep];
        __syncthreads();

        if (it + 1 < ntiles) {
            const float* kn = kbase + (size_t)(s0 + 64) * DD;
#pragma unroll
            for (int rep = 0; rep < 4; rep++)
                pf[rep] = *(const float4*)&kn[(size_t)(prr + rep * 16) * DD + pc4 * 4];
        }

        float sc[8][4];
#pragma unroll
        for (int i = 0; i < 8; i++)
#pragma unroll
            for (int j = 0; j < 4; j++) sc[i][j] = 0.f;

#pragma unroll
        for (int d4 = 0; d4 < 16; d4++) {
            float4 kv[4];
#pragma unroll
            for (int j = 0; j < 4; j++)
                kv[j] = *(const float4*)&kv_sm[tx * 4 + j][d4 * 4];
#pragma unroll
            for (int i = 0; i < 8; i++) {
                float4 qv = *(const float4*)&q_sm[ty * 8 + i][d4 * 4];
#pragma unroll
                for (int j = 0; j < 4; j++)
                    sc[i][j] += qv.x * kv[j].x + qv.y * kv[j].y +
                                qv.z * kv[j].z + qv.w * kv[j].w;
            }
        }

#pragma unroll
        for (int i = 0; i < 8; i++) {
            const int row = ty * 8 + i;
            const int t = t0 + row;
#pragma unroll
            for (int j = 0; j < 4; j++) {
                int s = s0 + tx * 4 + j;
                sc[i][j] = (s <= t) ? sc[i][j] * 0.125f : -1e30f;
            }
            float tm = fmaxf(fmaxf(sc[i][0], sc[i][1]),
                             fmaxf(sc[i][2], sc[i][3]));
#pragma unroll
            for (int off = 1; off < 16; off <<= 1)
                tm = fmaxf(tm, __shfl_xor_sync(0xffffffffu, tm, off));
            float mn = fmaxf(m[i], tm);
            float ev[4], ls = 0.f;
#pragma unroll
            for (int j = 0; j < 4; j++) {
                ev[j] = __expf(sc[i][j] - mn);
                ls += ev[j];
            }
#pragma unroll
            for (int off = 1; off < 16; off <<= 1)
                ls += __shfl_xor_sync(0xffffffffu, ls, off);
            l[i] = l[i] * __expf(m[i] - mn) + ls;
            m[i] = mn;
            if (tx == 0) mh[row][it] = mn;
            float* erow = g_e + ((size_t)(bh * TT + t)) * TT;
            *(float4*)&erow[s0 + tx * 4] =
                make_float4(ev[0], ev[1], ev[2], ev[3]);
        }
        __syncthreads();
    }

    // Per-tile rescale factors c_it = exp(m_it - m_final) / l
#pragma unroll
    for (int i = 0; i < 8; i++) {
        const float inv_l = 1.0f / l[i];
        for (int it = tx; it < ntiles; it += 16)
            mh[ty * 8 + i][it] = __expf(mh[ty * 8 + i][it] - m[i]) * inv_l;
    }
    __syncthreads();

    float oacc[8][4];
#pragma unroll
    for (int i = 0; i < 8; i++)
#pragma unroll
        for (int j = 0; j < 4; j++) oacc[i][j] = 0.f;

    // Prefetch V tile 0
#pragma unroll
    for (int rep = 0; rep < 4; rep++)
        pf[rep] = *(const float4*)&vbase[(size_t)(prr + rep * 16) * DD + pc4 * 4];

    // ---------------- Pass 2: sparsify cached e, A @ V ----------------
    for (int it = 0; it < ntiles; it++) {
        const int s0 = it * 64;
#pragma unroll
        for (int rep = 0; rep < 4; rep++)
            *(float4*)&kv_sm[prr + rep * 16][pc4 * 4] = pf[rep];

#pragma unroll
        for (int i = 0; i < 8; i++) {
            const int row = ty * 8 + i;
            const int t = t0 + row;
            const float fac = mh[row][it];
            const float* erow = g_e + ((size_t)(bh * TT + t)) * TT;
            float4 ev = *(const float4*)&erow[s0 + tx * 4];
            uint32_t word = g_mask[((size_t)(bh * TT + t)) * (TT / 32) +
                                   (s0 >> 5) + (tx >> 3)];
            int bp = (tx & 7) * 4;
            float a0 = ev.x * fac, a1 = ev.y * fac,
                  a2 = ev.z * fac, a3 = ev.w * fac;
            a0 = (a0 > 0.01f || ((word >> (bp + 0)) & 1u)) ? a0 : 0.f;
            a1 = (a1 > 0.01f || ((word >> (bp + 1)) & 1u)) ? a1 : 0.f;
            a2 = (a2 > 0.01f || ((word >> (bp + 2)) & 1u)) ? a2 : 0.f;
            a3 = (a3 > 0.01f || ((word >> (bp + 3)) & 1u)) ? a3 : 0.f;
            *(float4*)&a_sm[row][tx * 4] = make_float4(a0, a1, a2, a3);
        }
        __syncthreads();

        if (it + 1 < ntiles) {
            const float* vn = vbase + (size_t)(s0 + 64) * DD;
#pragma unroll
            for (int rep = 0; rep < 4; rep++)
                pf[rep] = *(const float4*)&vn[(size_t)(prr + rep * 16) * DD + pc4 * 4];
        }

#pragma unroll
        for (int sg = 0; sg < 16; sg++) {
            float4 v4[4];
#pragma unroll
            for (int k = 0; k < 4; k++)
                v4[k] = *(const float4*)&kv_sm[sg * 4 + k][tx * 4];
#pragma unroll
            for (int i = 0; i < 8; i++) {
                float4 a4 = *(const float4*)&a_sm[ty * 8 + i][sg * 4];
                oacc[i][0] += a4.x * v4[0].x + a4.y * v4[1].x +
                              a4.z * v4[2].x + a4.w * v4[3].x;
                oacc[i][1] += a4.x * v4[0].y + a4.y * v4[1].y +
                              a4.z * v4[2].y + a4.w * v4[3].y;
                oacc[i][2] += a4.x * v4[0].z + a4.y * v4[1].z +
                              a4.z * v4[2].z + a4.w * v4[3].z;
                oacc[i][3] += a4.x * v4[0].w + a4.y * v4[1].w +
                              a4.z * v4[2].w + a4.w * v4[3].w;
            }
        }
        __syncthreads();
    }

    // Store to [B, T, C] with c = h*64 + d, d = tx*4..tx*4+3
    const int b = blockIdx.z, h = blockIdx.y;
#pragma unroll
    for (int i = 0; i < 8; i++) {
        const int t = t0 + ty * 8 + i;
        float* dst = g_ao + ((size_t)(b * TT + t) * CC) + h * 64 + tx * 4;
        *(float4*)dst = make_float4(oacc[i][0], oacc[i][1],
                                    oacc[i][2], oacc[i][3]);
    }
}

// ---------------------------------------------------------------------------
extern "C" void kernel_launch(void* const* d_in, const int* in_sizes, int n_in,
                              void* d_out, int out_size) {
    const float* x    = (const float*)d_in[0];
    const float* Wqkv = (const float*)d_in[1];
    const float* bqkv = (const float*)d_in[2];
    const float* Wout = (const float*)d_in[3];
    const float* bout = (const float*)d_in[4];
    float* out = (float*)d_out;

    const int ATTN_SMEM = (320 * 68 + 128 * 32) * 4;  // 103424 B
    cudaFuncSetAttribute(attn_kernel,
                         cudaFuncAttributeMaxDynamicSharedMemorySize,
                         ATTN_SMEM);

    // 0) Regrow bitmask (input-independent)
    mask_kernel<<<dim3(8, TT, BB * HH), 256>>>();

    // 1) QKV projection, scattered to [B,H,T,D]
    gemm_kernel<<<dim3(3 * CC / 128, BB * TT / 128), 256>>>(
        x, Wqkv, bqkv, nullptr, BB * TT, 3 * CC, CC, 1);

    // 2) Causal attention + neuroplastic sparsification
    attn_kernel<<<dim3(TT / 128, HH, BB), 256, ATTN_SMEM>>>();

    // 3) Output projection
    gemm_kernel<<<dim3(CC / 128, BB * TT / 128), 256>>>(
        nullptr, Wout, bout, out, BB * TT, CC, CC, 0);
}

// round 8
// speedup vs baseline: 1.4195x; 1.4195x over previous
#include <cuda_runtime.h>
#include <cuda_bf16.h>
#include <stdint.h>

#define BB 2
#define TT 2048
#define CC 1024
#define HH 16
#define DD 64

// ---------------------------------------------------------------------------
// Scratch (allocation-free rule: __device__ globals).
// NOTE: these are ONLY referenced from device code — never as host-side
// kernel arguments (host reference yields the host shadow address).
// ---------------------------------------------------------------------------
__device__ float g_q[BB * HH * TT * DD];
__device__ float g_k[BB * HH * TT * DD];
__device__ float g_v[BB * HH * TT * DD];
__device__ float g_ao[BB * TT * CC];
__device__ float g_e[(size_t)BB * HH * TT * TT];
__device__ uint32_t g_mask[(size_t)BB * HH * TT * (TT / 32)];
// bf16 split operands
__device__ __nv_bfloat16 g_xh[BB * TT * CC], g_xl[BB * TT * CC];
__device__ __nv_bfloat16 g_wqh[3 * CC * CC], g_wql[3 * CC * CC];   // Wqkv^T
__device__ __nv_bfloat16 g_woh[CC * CC], g_wol[CC * CC];           // Wout^T
__device__ __nv_bfloat16 g_aoh[BB * TT * CC], g_aol[BB * TT * CC];

// ---------------------------------------------------------------------------
// sm_80-level PTX helpers (valid on compute_103 virtual arch)
// ---------------------------------------------------------------------------
__device__ __forceinline__ uint32_t smem_u32(const void* p) {
    uint32_t a;
    asm("{ .reg .u64 t; cvta.to.shared.u64 t, %1; cvt.u32.u64 %0, t; }"
        : "=r"(a) : "l"(p));
    return a;
}
__device__ __forceinline__ void cp16(uint32_t dst, const void* src) {
    asm volatile("cp.async.cg.shared.global [%0], [%1], 16;"
                 :: "r"(dst), "l"(src) : "memory");
}
#define CP_COMMIT() asm volatile("cp.async.commit_group;" ::: "memory")
#define CP_WAIT(n)  asm volatile("cp.async.wait_group %0;" :: "n"(n) : "memory")

__device__ __forceinline__ void mma16816(float* c, const uint32_t* a,
                                         const uint32_t* b) {
    asm volatile(
        "mma.sync.aligned.m16n8k16.row.col.f32.bf16.bf16.f32 "
        "{%0,%1,%2,%3},{%4,%5,%6,%7},{%8,%9},{%0,%1,%2,%3};"
        : "+f"(c[0]), "+f"(c[1]), "+f"(c[2]), "+f"(c[3])
        : "r"(a[0]), "r"(a[1]), "r"(a[2]), "r"(a[3]), "r"(b[0]), "r"(b[1]));
}

// ---------------------------------------------------------------------------
// Threefry-2x32, key = (0, 42)
// ---------------------------------------------------------------------------
__device__ __forceinline__ uint2 threefry_0_42(uint32_t x0, uint32_t x1) {
    const uint32_t ks0 = 0u, ks1 = 42u;
    const uint32_t ks2 = 0x1BD11BDAu ^ ks0 ^ ks1;
    x0 += ks0; x1 += ks1;
#define TF_RND(rot) { x0 += x1; x1 = __funnelshift_l(x1, x1, (rot)); x1 ^= x0; }
    TF_RND(13) TF_RND(15) TF_RND(26) TF_RND(6)
    x0 += ks1; x1 += ks2 + 1u;
    TF_RND(17) TF_RND(29) TF_RND(16) TF_RND(24)
    x0 += ks2; x1 += ks0 + 2u;
    TF_RND(13) TF_RND(15) TF_RND(26) TF_RND(6)
    x0 += ks0; x1 += ks1 + 3u;
    TF_RND(17) TF_RND(29) TF_RND(16) TF_RND(24)
    x0 += ks1; x1 += ks2 + 4u;
    TF_RND(13) TF_RND(15) TF_RND(26) TF_RND(6)
    x0 += ks2; x1 += ks0 + 5u;
#undef TF_RND
    return make_uint2(x0, x1);
}
__device__ __forceinline__ bool regrow_test(uint32_t idx) {
    uint2 rb = threefry_0_42(0u, idx);
    return ((rb.x ^ rb.y) >> 9) <= 419430u;
}

__global__ void __launch_bounds__(256)
mask_kernel() {
    const int t  = blockIdx.y;
    const int bh = blockIdx.z;
    const int w  = blockIdx.x * 8 + (threadIdx.x >> 5);
    if (w * 32 > t) return;
    const int lane = threadIdx.x & 31;
    const uint32_t s = (uint32_t)(w * 32 + lane);
    const uint32_t idx = ((uint32_t)(bh * TT + t)) * (uint32_t)TT + s;
    uint32_t word = __ballot_sync(0xffffffffu, regrow_test(idx));
    if (lane == 0) g_mask[((size_t)(bh * TT + t)) * (TT / 32) + w] = word;
}

// ---------------------------------------------------------------------------
// fp32 -> bf16 hi/lo split.  sel 0: X(arg) -> g_xh/g_xl
//                            sel 1: g_ao   -> g_aoh/g_aol
// ---------------------------------------------------------------------------
__global__ void __launch_bounds__(256)
conv_rows(const float* __restrict__ X, int sel, int n4) {
    const float* src = (sel == 0) ? X : (const float*)g_ao;
    __nv_bfloat16* Xh = (sel == 0) ? g_xh : g_aoh;
    __nv_bfloat16* Xl = (sel == 0) ? g_xl : g_aol;
    int i = blockIdx.x * 256 + threadIdx.x;
    if (i >= n4) return;
    float4 v = ((const float4*)src)[i];
    float vv[4] = {v.x, v.y, v.z, v.w};
    __nv_bfloat16 h[4], l[4];
#pragma unroll
    for (int j = 0; j < 4; j++) {
        h[j] = __float2bfloat16(vv[j]);
        l[j] = __float2bfloat16(vv[j] - __bfloat162float(h[j]));
    }
    *(__nv_bfloat162*)&Xh[i * 4]     = __nv_bfloat162(h[0], h[1]);
    *(__nv_bfloat162*)&Xh[i * 4 + 2] = __nv_bfloat162(h[2], h[3]);
    *(__nv_bfloat162*)&Xl[i * 4]     = __nv_bfloat162(l[0], l[1]);
    *(__nv_bfloat162*)&Xl[i * 4 + 2] = __nv_bfloat162(l[2], l[3]);
}

// W [K][N] fp32 -> W^T [N][K] bf16 hi/lo.  sel 0: g_wqh/g_wql, 1: g_woh/g_wol
__global__ void __launch_bounds__(256)
conv_tr(const float* __restrict__ W, int K, int N, int sel) {
    __shared__ float sm[32][33];
    __nv_bfloat16* Th = (sel == 0) ? g_wqh : g_woh;
    __nv_bfloat16* Tl = (sel == 0) ? g_wql : g_wol;
    const int n0 = blockIdx.x * 32, k0 = blockIdx.y * 32;
    const int tx = threadIdx.x, ty = threadIdx.y;
#pragma unroll
    for (int i = 0; i < 4; i++)
        sm[ty + i * 8][tx] = W[(size_t)(k0 + ty + i * 8) * N + n0 + tx];
    __syncthreads();
#pragma unroll
    for (int i = 0; i < 4; i++) {
        float v = sm[tx][ty + i * 8];
        __nv_bfloat16 h = __float2bfloat16(v);
        __nv_bfloat16 l = __float2bfloat16(v - __bfloat162float(h));
        size_t o = (size_t)(n0 + ty + i * 8) * K + k0 + tx;
        Th[o] = h; Tl[o] = l;
    }
}

// ---------------------------------------------------------------------------
// Split-bf16 HMMA GEMM: C = A @ Bt^T + bias.  Operands chosen in-kernel:
//   sel 0: A = g_xh/g_xl [4096][1024],  Bt = g_wqh/g_wql [3072][1024],
//          epilogue scatters into g_q/g_k/g_v (QKV).
//   sel 1: A = g_aoh/g_aol [4096][1024], Bt = g_woh/g_wol [1024][1024],
//          row-major store into Cout.
// 128x128 CTA tile, 256 thr (8 warps, 4x2), K-chunks 32, cp.async dbl-buffer.
// ---------------------------------------------------------------------------
#define GOPE   (128 * 40)           // elems per operand per stage (row pad 40)
#define GSTAGE (4 * GOPE)           // elems per stage
#define GEMM_SMEM (2 * GSTAGE * 2)  // bytes = 81920

__global__ void __launch_bounds__(256)
hmma_gemm(const float* __restrict__ bias, float* __restrict__ Cout, int sel) {
    extern __shared__ __nv_bfloat16 gsm[];
    const __nv_bfloat16* Ah = (sel == 0) ? g_xh : g_aoh;
    const __nv_bfloat16* Al = (sel == 0) ? g_xl : g_aol;
    const __nv_bfloat16* Bh = (sel == 0) ? g_wqh : g_woh;
    const __nv_bfloat16* Bl = (sel == 0) ? g_wql : g_wol;
    const int Kdim = CC;
    const int Ncols = (sel == 0) ? 3 * CC : CC;

    const int tid = threadIdx.x;
    const int lane = tid & 31, wid = tid >> 5;
    const int wm = wid & 3, wn = wid >> 2;      // 4 x 2 warp grid
    const int n0 = blockIdx.x * 128, m0 = blockIdx.y * 128;
    const int g = lane >> 2, j2 = (lane & 3) * 2;

    float acc[2][8][4];
#pragma unroll
    for (int mi = 0; mi < 2; mi++)
#pragma unroll
        for (int ni = 0; ni < 8; ni++)
#pragma unroll
            for (int r = 0; r < 4; r++) acc[mi][ni][r] = 0.f;

    const int nch = Kdim / 32;

#define ISSUE_LOADS(IT, STAGE) do {                                          \
        const int _k0 = (IT) * 32;                                          \
        __nv_bfloat16* _sb = gsm + (STAGE) * GSTAGE;                         \
        _Pragma("unroll")                                                    \
        for (int _r = 0; _r < 2; _r++) {                                     \
            int _c = _r * 256 + tid;                                         \
            int _row = _c >> 2, _off = (_c & 3) * 8;                         \
            uint32_t _so = smem_u32(_sb + _row * 40 + _off);                 \
            size_t _ga = (size_t)(m0 + _row) * Kdim + _k0 + _off;            \
            size_t _gb = (size_t)(n0 + _row) * Kdim + _k0 + _off;            \
            cp16(_so,                 Ah + _ga);                             \
            cp16(_so + 2 * GOPE,      Al + _ga);                             \
            cp16(_so + 4 * GOPE,      Bh + _gb);                             \
            cp16(_so + 6 * GOPE,      Bl + _gb);                             \
        }                                                                    \
    } while (0)

    ISSUE_LOADS(0, 0);
    CP_COMMIT();

    for (int it = 0; it < nch; it++) {
        if (it + 1 < nch) {
            ISSUE_LOADS(it + 1, (it + 1) & 1);
            CP_COMMIT();
            CP_WAIT(1);
        } else {
            CP_WAIT(0);
        }
        __syncthreads();

        const __nv_bfloat16* sAh = gsm + (it & 1) * GSTAGE;
        const __nv_bfloat16* sAl = sAh + GOPE;
        const __nv_bfloat16* sBh = sAh + 2 * GOPE;
        const __nv_bfloat16* sBl = sAh + 3 * GOPE;

#pragma unroll
        for (int ks = 0; ks < 2; ks++) {
            const int k0 = ks * 16;
            uint32_t ah[2][4], al[2][4], bh[8][2], bl[8][2];
#pragma unroll
            for (int mi = 0; mi < 2; mi++) {
                int row = wm * 32 + mi * 16;
                ah[mi][0] = *(const uint32_t*)&sAh[(row + g) * 40 + k0 + j2];
                ah[mi][1] = *(const uint32_t*)&sAh[(row + 8 + g) * 40 + k0 + j2];
                ah[mi][2] = *(const uint32_t*)&sAh[(row + g) * 40 + k0 + j2 + 8];
                ah[mi][3] = *(const uint32_t*)&sAh[(row + 8 + g) * 40 + k0 + j2 + 8];
                al[mi][0] = *(const uint32_t*)&sAl[(row + g) * 40 + k0 + j2];
                al[mi][1] = *(const uint32_t*)&sAl[(row + 8 + g) * 40 + k0 + j2];
                al[mi][2] = *(const uint32_t*)&sAl[(row + g) * 40 + k0 + j2 + 8];
                al[mi][3] = *(const uint32_t*)&sAl[(row + 8 + g) * 40 + k0 + j2 + 8];
            }
#pragma unroll
            for (int ni = 0; ni < 8; ni++) {
                int n = wn * 64 + ni * 8 + g;
                bh[ni][0] = *(const uint32_t*)&sBh[n * 40 + k0 + j2];
                bh[ni][1] = *(const uint32_t*)&sBh[n * 40 + k0 + j2 + 8];
                bl[ni][0] = *(const uint32_t*)&sBl[n * 40 + k0 + j2];
                bl[ni][1] = *(const uint32_t*)&sBl[n * 40 + k0 + j2 + 8];
            }
#pragma unroll
            for (int mi = 0; mi < 2; mi++)
#pragma unroll
                for (int ni = 0; ni < 8; ni++) {
                    mma16816(acc[mi][ni], ah[mi], bh[ni]);
                    mma16816(acc[mi][ni], ah[mi], bl[ni]);
                    mma16816(acc[mi][ni], al[mi], bh[ni]);
                }
        }
        __syncthreads();
    }

    // epilogue: c0,c1 -> (m_r, n_c..+1); c2,c3 -> (m_r+8, n_c..+1)
#pragma unroll
    for (int mi = 0; mi < 2; mi++) {
#pragma unroll
        for (int ni = 0; ni < 8; ni++) {
            int m_r = m0 + wm * 32 + mi * 16 + g;
            int n_c = n0 + wn * 64 + ni * 8 + j2;
            float b0 = bias[n_c], b1 = bias[n_c + 1];
            float v00 = acc[mi][ni][0] + b0, v01 = acc[mi][ni][1] + b1;
            float v10 = acc[mi][ni][2] + b0, v11 = acc[mi][ni][3] + b1;
            if (sel == 1) {
                *(float2*)&Cout[(size_t)m_r * Ncols + n_c] = make_float2(v00, v01);
                *(float2*)&Cout[(size_t)(m_r + 8) * Ncols + n_c] = make_float2(v10, v11);
            } else {
                int part = n_c >> 10, rem = n_c & 1023;
                int h = rem >> 6, dd = rem & 63;
                float* dst = (part == 0) ? g_q : (part == 1) ? g_k : g_v;
                int b = m_r >> 11, t = m_r & 2047;
                *(float2*)&dst[((((size_t)b * HH) + h) * TT + t) * DD + dd] =
                    make_float2(v00, v01);
                int b2 = (m_r + 8) >> 11, t2 = (m_r + 8) & 2047;
                *(float2*)&dst[((((size_t)b2 * HH) + h) * TT + t2) * DD + dd] =
                    make_float2(v10, v11);
            }
        }
    }
#undef ISSUE_LOADS
}

// ---------------------------------------------------------------------------
// Attention: paired q-tiles (qb, NQB-1-qb) per block for perfect balance.
// Per tile: 128 q-rows, 64-key tiles, 256 thr, 8x4 micro-tile,
// cached exponentials + precomputed regrow bitmask.
// ---------------------------------------------------------------------------
__global__ void __launch_bounds__(256)
attn_kernel() {
    extern __shared__ float asmem[];
    float (*q_sm)[68]  = (float(*)[68])(asmem);
    float (*kv_sm)[68] = (float(*)[68])(asmem + 128 * 68);
    float (*a_sm)[68]  = (float(*)[68])(asmem + 192 * 68);
    float (*mh)[32]    = (float(*)[32])(asmem + 320 * 68);

    const int NQB = TT / 128;
    const int bh = blockIdx.z * HH + blockIdx.y;
    const int tid = threadIdx.x;
    const int ty = tid >> 4;
    const int tx = tid & 15;

    const float* qbase = g_q + ((size_t)bh * TT) * DD;
    const float* kbase = g_k + ((size_t)bh * TT) * DD;
    const float* vbase = g_v + ((size_t)bh * TT) * DD;
    const int prr = tid >> 4, pc4 = tid & 15;

    for (int half = 0; half < 2; half++) {
        const int qb = half == 0 ? (NQB - 1 - (int)blockIdx.x) : (int)blockIdx.x;
        const int t0 = qb * 128;

#pragma unroll
        for (int rep = 0; rep < 8; rep++) {
            int e = tid + rep * 256;
            int rr = e >> 4, c4 = e & 15;
            *(float4*)&q_sm[rr][c4 * 4] =
                *(const float4*)&qbase[(size_t)(t0 + rr) * DD + c4 * 4];
        }

        const int ntiles = 2 * qb + 2;
        float m[8], l[8];
#pragma unroll
        for (int i = 0; i < 8; i++) { m[i] = -1e30f; l[i] = 0.f; }

        float4 pf[4];
#pragma unroll
        for (int rep = 0; rep < 4; rep++)
            pf[rep] = *(const float4*)&kbase[(size_t)(prr + rep * 16) * DD + pc4 * 4];

        // ---------------- Pass 1: QK, online max/sum, cache e ----------------
        for (int it = 0; it < ntiles; it++) {
            const int s0 = it * 64;
#pragma unroll
            for (int rep = 0; rep < 4; rep++)
                *(float4*)&kv_sm[prr + rep * 16][pc4 * 4] = pf[rep];
            __syncthreads();
            if (it + 1 < ntiles) {
                const float* kn = kbase + (size_t)(s0 + 64) * DD;
#pragma unroll
                for (int rep = 0; rep < 4; rep++)
                    pf[rep] = *(const float4*)&kn[(size_t)(prr + rep * 16) * DD + pc4 * 4];
            }

            float sc[8][4];
#pragma unroll
            for (int i = 0; i < 8; i++)
#pragma unroll
                for (int j = 0; j < 4; j++) sc[i][j] = 0.f;
#pragma unroll
            for (int d4 = 0; d4 < 16; d4++) {
                float4 kv[4];
#pragma unroll
                for (int j = 0; j < 4; j++)
                    kv[j] = *(const float4*)&kv_sm[tx * 4 + j][d4 * 4];
#pragma unroll
                for (int i = 0; i < 8; i++) {
                    float4 qv = *(const float4*)&q_sm[ty * 8 + i][d4 * 4];
#pragma unroll
                    for (int j = 0; j < 4; j++)
                        sc[i][j] += qv.x * kv[j].x + qv.y * kv[j].y +
                                    qv.z * kv[j].z + qv.w * kv[j].w;
                }
            }

#pragma unroll
            for (int i = 0; i < 8; i++) {
                const int row = ty * 8 + i;
                const int t = t0 + row;
#pragma unroll
                for (int j = 0; j < 4; j++) {
                    int s = s0 + tx * 4 + j;
                    sc[i][j] = (s <= t) ? sc[i][j] * 0.125f : -1e30f;
                }
                float tm = fmaxf(fmaxf(sc[i][0], sc[i][1]),
                                 fmaxf(sc[i][2], sc[i][3]));
#pragma unroll
                for (int off = 1; off < 16; off <<= 1)
                    tm = fmaxf(tm, __shfl_xor_sync(0xffffffffu, tm, off));
                float mn = fmaxf(m[i], tm);
                float ev[4], ls = 0.f;
#pragma unroll
                for (int j = 0; j < 4; j++) {
                    ev[j] = __expf(sc[i][j] - mn);
                    ls += ev[j];
                }
#pragma unroll
                for (int off = 1; off < 16; off <<= 1)
                    ls += __shfl_xor_sync(0xffffffffu, ls, off);
                l[i] = l[i] * __expf(m[i] - mn) + ls;
                m[i] = mn;
                if (tx == 0) mh[row][it] = mn;
                float* erow = g_e + ((size_t)(bh * TT + t)) * TT;
                *(float4*)&erow[s0 + tx * 4] = make_float4(ev[0], ev[1], ev[2], ev[3]);
            }
            __syncthreads();
        }

#pragma unroll
        for (int i = 0; i < 8; i++) {
            const float inv_l = 1.0f / l[i];
            for (int it = tx; it < ntiles; it += 16)
                mh[ty * 8 + i][it] = __expf(mh[ty * 8 + i][it] - m[i]) * inv_l;
        }
        __syncthreads();

        float oacc[8][4];
#pragma unroll
        for (int i = 0; i < 8; i++)
#pragma unroll
            for (int j = 0; j < 4; j++) oacc[i][j] = 0.f;

#pragma unroll
        for (int rep = 0; rep < 4; rep++)
            pf[rep] = *(const float4*)&vbase[(size_t)(prr + rep * 16) * DD + pc4 * 4];

        // ---------------- Pass 2: sparsify cached e, A @ V ----------------
        for (int it = 0; it < ntiles; it++) {
            const int s0 = it * 64;
#pragma unroll
            for (int rep = 0; rep < 4; rep++)
                *(float4*)&kv_sm[prr + rep * 16][pc4 * 4] = pf[rep];

#pragma unroll
            for (int i = 0; i < 8; i++) {
                const int row = ty * 8 + i;
                const int t = t0 + row;
                const float fac = mh[row][it];
                const float* erow = g_e + ((size_t)(bh * TT + t)) * TT;
                float4 ev = *(const float4*)&erow[s0 + tx * 4];
                uint32_t word = g_mask[((size_t)(bh * TT + t)) * (TT / 32) +
                                       (s0 >> 5) + (tx >> 3)];
                int bp = (tx & 7) * 4;
                float a0 = ev.x * fac, a1 = ev.y * fac,
                      a2 = ev.z * fac, a3 = ev.w * fac;
                a0 = (a0 > 0.01f || ((word >> (bp + 0)) & 1u)) ? a0 : 0.f;
                a1 = (a1 > 0.01f || ((word >> (bp + 1)) & 1u)) ? a1 : 0.f;
                a2 = (a2 > 0.01f || ((word >> (bp + 2)) & 1u)) ? a2 : 0.f;
                a3 = (a3 > 0.01f || ((word >> (bp + 3)) & 1u)) ? a3 : 0.f;
                *(float4*)&a_sm[row][tx * 4] = make_float4(a0, a1, a2, a3);
            }
            __syncthreads();

            if (it + 1 < ntiles) {
                const float* vn = vbase + (size_t)(s0 + 64) * DD;
#pragma unroll
                for (int rep = 0; rep < 4; rep++)
                    pf[rep] = *(const float4*)&vn[(size_t)(prr + rep * 16) * DD + pc4 * 4];
            }

#pragma unroll
            for (int sg = 0; sg < 16; sg++) {
                float4 v4[4];
#pragma unroll
                for (int k = 0; k < 4; k++)
                    v4[k] = *(const float4*)&kv_sm[sg * 4 + k][tx * 4];
#pragma unroll
                for (int i = 0; i < 8; i++) {
                    float4 a4 = *(const float4*)&a_sm[ty * 8 + i][sg * 4];
                    oacc[i][0] += a4.x * v4[0].x + a4.y * v4[1].x +
                                  a4.z * v4[2].x + a4.w * v4[3].x;
                    oacc[i][1] += a4.x * v4[0].y + a4.y * v4[1].y +
                                  a4.z * v4[2].y + a4.w * v4[3].y;
                    oacc[i][2] += a4.x * v4[0].z + a4.y * v4[1].z +
                                  a4.z * v4[2].z + a4.w * v4[3].z;
                    oacc[i][3] += a4.x * v4[0].w + a4.y * v4[1].w +
                                  a4.z * v4[2].w + a4.w * v4[3].w;
                }
            }
            __syncthreads();
        }

        const int b = blockIdx.z, h = blockIdx.y;
#pragma unroll
        for (int i = 0; i < 8; i++) {
            const int t = t0 + ty * 8 + i;
            float* dst = g_ao + ((size_t)(b * TT + t) * CC) + h * 64 + tx * 4;
            *(float4*)dst = make_float4(oacc[i][0], oacc[i][1],
                                        oacc[i][2], oacc[i][3]);
        }
        __syncthreads();
    }
}

// ---------------------------------------------------------------------------
extern "C" void kernel_launch(void* const* d_in, const int* in_sizes, int n_in,
                              void* d_out, int out_size) {
    const float* x    = (const float*)d_in[0];
    const float* Wqkv = (const float*)d_in[1];
    const float* bqkv = (const float*)d_in[2];
    const float* Wout = (const float*)d_in[3];
    const float* bout = (const float*)d_in[4];
    float* out = (float*)d_out;

    const int ATTN_SMEM = (320 * 68 + 128 * 32) * 4;  // 103424 B
    cudaFuncSetAttribute(attn_kernel,
                         cudaFuncAttributeMaxDynamicSharedMemorySize, ATTN_SMEM);
    cudaFuncSetAttribute(hmma_gemm,
                         cudaFuncAttributeMaxDynamicSharedMemorySize, GEMM_SMEM);

    // 0) Regrow bitmask (input-independent)
    mask_kernel<<<dim3(8, TT, BB * HH), 256>>>();

    // 1) Split-bf16 conversions: x -> g_xh/g_xl, Wqkv^T, Wout^T
    conv_rows<<<(BB * TT * CC / 4 + 255) / 256, 256>>>(x, 0, BB * TT * CC / 4);
    conv_tr<<<dim3(3 * CC / 32, CC / 32), dim3(32, 8)>>>(Wqkv, CC, 3 * CC, 0);
    conv_tr<<<dim3(CC / 32, CC / 32), dim3(32, 8)>>>(Wout, CC, CC, 1);

    // 2) QKV projection (HMMA split-bf16), scattered to [B,H,T,D]
    hmma_gemm<<<dim3(3 * CC / 128, BB * TT / 128), 256, GEMM_SMEM>>>(
        bqkv, nullptr, 0);

    // 3) Causal attention + neuroplastic sparsification (paired tiles)
    attn_kernel<<<dim3(TT / 256, HH, BB), 256, ATTN_SMEM>>>();

    // 4) Convert attention output, then output projection (HMMA)
    conv_rows<<<(BB * TT * CC / 4 + 255) / 256, 256>>>(nullptr, 1,
                                                       BB * TT * CC / 4);
    hmma_gemm<<<dim3(CC / 128, BB * TT / 128), 256, GEMM_SMEM>>>(
        bout, out, 1);
}

// round 9
// speedup vs baseline: 1.6507x; 1.1629x over previous
#include <cuda_runtime.h>
#include <cuda_bf16.h>
#include <stdint.h>

#define BB 2
#define TT 2048
#define CC 1024
#define HH 16
#define DD 64

// ---------------------------------------------------------------------------
// Scratch (allocation-free rule: __device__ globals). Only referenced from
// device code — never passed as host-side kernel arguments.
// ---------------------------------------------------------------------------
__device__ float g_q[BB * HH * TT * DD];
__device__ float g_k[BB * HH * TT * DD];
__device__ float g_v[BB * HH * TT * DD];
__device__ float g_e[(size_t)BB * HH * TT * TT];
__device__ uint32_t g_mask[(size_t)BB * HH * TT * (TT / 32)];
// bf16 split operands
__device__ __nv_bfloat16 g_xh[BB * TT * CC], g_xl[BB * TT * CC];
__device__ __nv_bfloat16 g_wqh[3 * CC * CC], g_wql[3 * CC * CC];   // Wqkv^T
__device__ __nv_bfloat16 g_woh[CC * CC], g_wol[CC * CC];           // Wout^T
__device__ __nv_bfloat16 g_aoh[BB * TT * CC], g_aol[BB * TT * CC];
// V transposed per (b,h): [bh][d][t], bf16 hi/lo
__device__ __nv_bfloat16 g_vth[(size_t)BB * HH * DD * TT];
__device__ __nv_bfloat16 g_vtl[(size_t)BB * HH * DD * TT];

// ---------------------------------------------------------------------------
// sm_80-level PTX helpers (valid on compute_103 virtual arch)
// ---------------------------------------------------------------------------
__device__ __forceinline__ uint32_t smem_u32(const void* p) {
    uint32_t a;
    asm("{ .reg .u64 t; cvta.to.shared.u64 t, %1; cvt.u32.u64 %0, t; }"
        : "=r"(a) : "l"(p));
    return a;
}
__device__ __forceinline__ void cp16(uint32_t dst, const void* src) {
    asm volatile("cp.async.cg.shared.global [%0], [%1], 16;"
                 :: "r"(dst), "l"(src) : "memory");
}
#define CP_COMMIT() asm volatile("cp.async.commit_group;" ::: "memory")
#define CP_WAIT(n)  asm volatile("cp.async.wait_group %0;" :: "n"(n) : "memory")

__device__ __forceinline__ void mma16816(float* c, const uint32_t* a,
                                         const uint32_t* b) {
    asm volatile(
        "mma.sync.aligned.m16n8k16.row.col.f32.bf16.bf16.f32 "
        "{%0,%1,%2,%3},{%4,%5,%6,%7},{%8,%9},{%0,%1,%2,%3};"
        : "+f"(c[0]), "+f"(c[1]), "+f"(c[2]), "+f"(c[3])
        : "r"(a[0]), "r"(a[1]), "r"(a[2]), "r"(a[3]), "r"(b[0]), "r"(b[1]));
}
__device__ __forceinline__ uint32_t pk(__nv_bfloat16 a, __nv_bfloat16 b) {
    return (uint32_t)__bfloat16_as_ushort(a) |
           ((uint32_t)__bfloat16_as_ushort(b) << 16);
}

// ---------------------------------------------------------------------------
// Threefry-2x32, key = (0, 42)
// ---------------------------------------------------------------------------
__device__ __forceinline__ uint2 threefry_0_42(uint32_t x0, uint32_t x1) {
    const uint32_t ks0 = 0u, ks1 = 42u;
    const uint32_t ks2 = 0x1BD11BDAu ^ ks0 ^ ks1;
    x0 += ks0; x1 += ks1;
#define TF_RND(rot) { x0 += x1; x1 = __funnelshift_l(x1, x1, (rot)); x1 ^= x0; }
    TF_RND(13) TF_RND(15) TF_RND(26) TF_RND(6)
    x0 += ks1; x1 += ks2 + 1u;
    TF_RND(17) TF_RND(29) TF_RND(16) TF_RND(24)
    x0 += ks2; x1 += ks0 + 2u;
    TF_RND(13) TF_RND(15) TF_RND(26) TF_RND(6)
    x0 += ks0; x1 += ks1 + 3u;
    TF_RND(17) TF_RND(29) TF_RND(16) TF_RND(24)
    x0 += ks1; x1 += ks2 + 4u;
    TF_RND(13) TF_RND(15) TF_RND(26) TF_RND(6)
    x0 += ks2; x1 += ks0 + 5u;
#undef TF_RND
    return make_uint2(x0, x1);
}
__device__ __forceinline__ bool regrow_test(uint32_t idx) {
    uint2 rb = threefry_0_42(0u, idx);
    return ((rb.x ^ rb.y) >> 9) <= 419430u;
}

__global__ void __launch_bounds__(256)
mask_kernel() {
    const int t  = blockIdx.y;
    const int bh = blockIdx.z;
    const int w  = blockIdx.x * 8 + (threadIdx.x >> 5);
    if (w * 32 > t) return;
    const int lane = threadIdx.x & 31;
    const uint32_t s = (uint32_t)(w * 32 + lane);
    const uint32_t idx = ((uint32_t)(bh * TT + t)) * (uint32_t)TT + s;
    uint32_t word = __ballot_sync(0xffffffffu, regrow_test(idx));
    if (lane == 0) g_mask[((size_t)(bh * TT + t)) * (TT / 32) + w] = word;
}

// ---------------------------------------------------------------------------
// fp32 -> bf16 hi/lo split: x -> g_xh/g_xl
// ---------------------------------------------------------------------------
__global__ void __launch_bounds__(256)
conv_rows(const float* __restrict__ X, int n4) {
    int i = blockIdx.x * 256 + threadIdx.x;
    if (i >= n4) return;
    float4 v = ((const float4*)X)[i];
    float vv[4] = {v.x, v.y, v.z, v.w};
    __nv_bfloat16 h[4], l[4];
#pragma unroll
    for (int j = 0; j < 4; j++) {
        h[j] = __float2bfloat16(vv[j]);
        l[j] = __float2bfloat16(vv[j] - __bfloat162float(h[j]));
    }
    ((uint32_t*)g_xh)[i * 2]     = pk(h[0], h[1]);
    ((uint32_t*)g_xh)[i * 2 + 1] = pk(h[2], h[3]);
    ((uint32_t*)g_xl)[i * 2]     = pk(l[0], l[1]);
    ((uint32_t*)g_xl)[i * 2 + 1] = pk(l[2], l[3]);
}

// W [K][N] fp32 -> W^T [N][K] bf16 hi/lo.  sel 0: g_wqh/g_wql, 1: g_woh/g_wol
__global__ void __launch_bounds__(256)
conv_tr(const float* __restrict__ W, int K, int N, int sel) {
    __shared__ float sm[32][33];
    __nv_bfloat16* Th = (sel == 0) ? g_wqh : g_woh;
    __nv_bfloat16* Tl = (sel == 0) ? g_wql : g_wol;
    const int n0 = blockIdx.x * 32, k0 = blockIdx.y * 32;
    const int tx = threadIdx.x, ty = threadIdx.y;
#pragma unroll
    for (int i = 0; i < 4; i++)
        sm[ty + i * 8][tx] = W[(size_t)(k0 + ty + i * 8) * N + n0 + tx];
    __syncthreads();
#pragma unroll
    for (int i = 0; i < 4; i++) {
        float v = sm[tx][ty + i * 8];
        __nv_bfloat16 h = __float2bfloat16(v);
        __nv_bfloat16 l = __float2bfloat16(v - __bfloat162float(h));
        size_t o = (size_t)(n0 + ty + i * 8) * K + k0 + tx;
        Th[o] = h; Tl[o] = l;
    }
}

// g_v [bh][t][d] fp32 -> g_vth/g_vtl [bh][d][t] bf16 hi/lo
__global__ void __launch_bounds__(256)
vt_split() {
    __shared__ float sm[32][33];
    const int bh = blockIdx.z;
    const int d0 = blockIdx.x * 32;
    const int t0 = blockIdx.y * 32;
    const int tx = threadIdx.x, ty = threadIdx.y;
    const float* src = g_v + (size_t)bh * TT * DD;
#pragma unroll
    for (int i = 0; i < 4; i++)
        sm[ty + i * 8][tx] = src[(size_t)(t0 + ty + i * 8) * DD + d0 + tx];
    __syncthreads();
#pragma unroll
    for (int i = 0; i < 4; i++) {
        float v = sm[tx][ty + i * 8];    // V[t0+tx][d0+ty+i*8]
        __nv_bfloat16 h = __float2bfloat16(v);
        __nv_bfloat16 l = __float2bfloat16(v - __bfloat162float(h));
        size_t o = ((size_t)bh * DD + d0 + ty + i * 8) * TT + t0 + tx;
        g_vth[o] = h; g_vtl[o] = l;
    }
}

// ---------------------------------------------------------------------------
// Split-bf16 HMMA GEMM (verified in R8): C = A @ Bt^T + bias.
//   sel 0: A=g_xh/g_xl, Bt=g_wqh/g_wql, epilogue scatters q/k/v.
//   sel 1: A=g_aoh/g_aol, Bt=g_woh/g_wol, row-major store to Cout.
// ---------------------------------------------------------------------------
#define GOPE   (128 * 40)
#define GSTAGE (4 * GOPE)
#define GEMM_SMEM (2 * GSTAGE * 2)

__global__ void __launch_bounds__(256)
hmma_gemm(const float* __restrict__ bias, float* __restrict__ Cout, int sel) {
    extern __shared__ __nv_bfloat16 gsm[];
    const __nv_bfloat16* Ah = (sel == 0) ? g_xh : g_aoh;
    const __nv_bfloat16* Al = (sel == 0) ? g_xl : g_aol;
    const __nv_bfloat16* Bh = (sel == 0) ? g_wqh : g_woh;
    const __nv_bfloat16* Bl = (sel == 0) ? g_wql : g_wol;
    const int Kdim = CC;
    const int Ncols = (sel == 0) ? 3 * CC : CC;

    const int tid = threadIdx.x;
    const int lane = tid & 31, wid = tid >> 5;
    const int wm = wid & 3, wn = wid >> 2;
    const int n0 = blockIdx.x * 128, m0 = blockIdx.y * 128;
    const int g = lane >> 2, j2 = (lane & 3) * 2;

    float acc[2][8][4];
#pragma unroll
    for (int mi = 0; mi < 2; mi++)
#pragma unroll
        for (int ni = 0; ni < 8; ni++)
#pragma unroll
            for (int r = 0; r < 4; r++) acc[mi][ni][r] = 0.f;

    const int nch = Kdim / 32;

#define ISSUE_LOADS(IT, STAGE) do {                                          \
        const int _k0 = (IT) * 32;                                          \
        __nv_bfloat16* _sb = gsm + (STAGE) * GSTAGE;                         \
        _Pragma("unroll")                                                    \
        for (int _r = 0; _r < 2; _r++) {                                     \
            int _c = _r * 256 + tid;                                         \
            int _row = _c >> 2, _off = (_c & 3) * 8;                         \
            uint32_t _so = smem_u32(_sb + _row * 40 + _off);                 \
            size_t _ga = (size_t)(m0 + _row) * Kdim + _k0 + _off;            \
            size_t _gb = (size_t)(n0 + _row) * Kdim + _k0 + _off;            \
            cp16(_so,                 Ah + _ga);                             \
            cp16(_so + 2 * GOPE,      Al + _ga);                             \
            cp16(_so + 4 * GOPE,      Bh + _gb);                             \
            cp16(_so + 6 * GOPE,      Bl + _gb);                             \
        }                                                                    \
    } while (0)

    ISSUE_LOADS(0, 0);
    CP_COMMIT();

    for (int it = 0; it < nch; it++) {
        if (it + 1 < nch) {
            ISSUE_LOADS(it + 1, (it + 1) & 1);
            CP_COMMIT();
            CP_WAIT(1);
        } else {
            CP_WAIT(0);
        }
        __syncthreads();

        const __nv_bfloat16* sAh = gsm + (it & 1) * GSTAGE;
        const __nv_bfloat16* sAl = sAh + GOPE;
        const __nv_bfloat16* sBh = sAh + 2 * GOPE;
        const __nv_bfloat16* sBl = sAh + 3 * GOPE;

#pragma unroll
        for (int ks = 0; ks < 2; ks++) {
            const int k0 = ks * 16;
            uint32_t ah[2][4], al[2][4], bh[8][2], bl[8][2];
#pragma unroll
            for (int mi = 0; mi < 2; mi++) {
                int row = wm * 32 + mi * 16;
                ah[mi][0] = *(const uint32_t*)&sAh[(row + g) * 40 + k0 + j2];
                ah[mi][1] = *(const uint32_t*)&sAh[(row + 8 + g) * 40 + k0 + j2];
                ah[mi][2] = *(const uint32_t*)&sAh[(row + g) * 40 + k0 + j2 + 8];
                ah[mi][3] = *(const uint32_t*)&sAh[(row + 8 + g) * 40 + k0 + j2 + 8];
                al[mi][0] = *(const uint32_t*)&sAl[(row + g) * 40 + k0 + j2];
                al[mi][1] = *(const uint32_t*)&sAl[(row + 8 + g) * 40 + k0 + j2];
                al[mi][2] = *(const uint32_t*)&sAl[(row + g) * 40 + k0 + j2 + 8];
                al[mi][3] = *(const uint32_t*)&sAl[(row + 8 + g) * 40 + k0 + j2 + 8];
            }
#pragma unroll
            for (int ni = 0; ni < 8; ni++) {
                int n = wn * 64 + ni * 8 + g;
                bh[ni][0] = *(const uint32_t*)&sBh[n * 40 + k0 + j2];
                bh[ni][1] = *(const uint32_t*)&sBh[n * 40 + k0 + j2 + 8];
                bl[ni][0] = *(const uint32_t*)&sBl[n * 40 + k0 + j2];
                bl[ni][1] = *(const uint32_t*)&sBl[n * 40 + k0 + j2 + 8];
            }
#pragma unroll
            for (int mi = 0; mi < 2; mi++)
#pragma unroll
                for (int ni = 0; ni < 8; ni++) {
                    mma16816(acc[mi][ni], ah[mi], bh[ni]);
                    mma16816(acc[mi][ni], ah[mi], bl[ni]);
                    mma16816(acc[mi][ni], al[mi], bh[ni]);
                }
        }
        __syncthreads();
    }

#pragma unroll
    for (int mi = 0; mi < 2; mi++) {
#pragma unroll
        for (int ni = 0; ni < 8; ni++) {
            int m_r = m0 + wm * 32 + mi * 16 + g;
            int n_c = n0 + wn * 64 + ni * 8 + j2;
            float b0 = bias[n_c], b1 = bias[n_c + 1];
            float v00 = acc[mi][ni][0] + b0, v01 = acc[mi][ni][1] + b1;
            float v10 = acc[mi][ni][2] + b0, v11 = acc[mi][ni][3] + b1;
            if (sel == 1) {
                *(float2*)&Cout[(size_t)m_r * Ncols + n_c] = make_float2(v00, v01);
                *(float2*)&Cout[(size_t)(m_r + 8) * Ncols + n_c] = make_float2(v10, v11);
            } else {
                int part = n_c >> 10, rem = n_c & 1023;
                int h = rem >> 6, dd = rem & 63;
                float* dst = (part == 0) ? g_q : (part == 1) ? g_k : g_v;
                int b = m_r >> 11, t = m_r & 2047;
                *(float2*)&dst[((((size_t)b * HH) + h) * TT + t) * DD + dd] =
                    make_float2(v00, v01);
                int b2 = (m_r + 8) >> 11, t2 = (m_r + 8) & 2047;
                *(float2*)&dst[((((size_t)b2 * HH) + h) * TT + t2) * DD + dd] =
                    make_float2(v10, v11);
            }
        }
    }
#undef ISSUE_LOADS
}

// ---------------------------------------------------------------------------
// Attention: paired q-tiles (qb, NQB-1-qb). Pass 1 = fp32 QK + online softmax
// (unchanged, scores precision frozen). Pass 2 = sparsify cached e, then
// AV via split-bf16 HMMA; output split written directly to g_aoh/g_aol.
// smem: [mh 16KB][q_sm | a_smh+a_sml 36KB][kv_sm | vt 18KB] = 71680 B.
// ---------------------------------------------------------------------------
#define ATTN_SMEM 71680

__global__ void __launch_bounds__(256, 2)
attn_kernel() {
    extern __shared__ float asmem[];
    float (*mh)[32]    = (float(*)[32])(asmem);
    float (*q_sm)[68]  = (float(*)[68])(asmem + 4096);
    float (*kv_sm)[68] = (float(*)[68])(asmem + 13312);
    __nv_bfloat16* a_smh  = (__nv_bfloat16*)(asmem + 4096);
    __nv_bfloat16* a_sml  = a_smh + 128 * 72;
    __nv_bfloat16* vt_smh = (__nv_bfloat16*)(asmem + 13312);
    __nv_bfloat16* vt_sml = vt_smh + 64 * 72;

    const int NQB = TT / 128;
    const int bh = blockIdx.z * HH + blockIdx.y;
    const int tid = threadIdx.x;
    const int ty = tid >> 4;
    const int tx = tid & 15;
    const int lane = tid & 31, wid = tid >> 5;
    const int wm = wid & 3, wn = wid >> 2;
    const int g = lane >> 2, j2 = (lane & 3) * 2;

    const float* qbase = g_q + ((size_t)bh * TT) * DD;
    const float* kbase = g_k + ((size_t)bh * TT) * DD;
    const int prr = tid >> 4, pc4 = tid & 15;

    for (int half = 0; half < 2; half++) {
        const int qb = half == 0 ? (NQB - 1 - (int)blockIdx.x) : (int)blockIdx.x;
        const int t0 = qb * 128;

#pragma unroll
        for (int rep = 0; rep < 8; rep++) {
            int e = tid + rep * 256;
            int rr = e >> 4, c4 = e & 15;
            *(float4*)&q_sm[rr][c4 * 4] =
                *(const float4*)&qbase[(size_t)(t0 + rr) * DD + c4 * 4];
        }

        const int ntiles = 2 * qb + 2;
        float m[8], l[8];
#pragma unroll
        for (int i = 0; i < 8; i++) { m[i] = -1e30f; l[i] = 0.f; }

        float4 pf[4];
#pragma unroll
        for (int rep = 0; rep < 4; rep++)
            pf[rep] = *(const float4*)&kbase[(size_t)(prr + rep * 16) * DD + pc4 * 4];

        // ------------- Pass 1: fp32 QK, online max/sum, cache e -------------
        for (int it = 0; it < ntiles; it++) {
            const int s0 = it * 64;
#pragma unroll
            for (int rep = 0; rep < 4; rep++)
                *(float4*)&kv_sm[prr + rep * 16][pc4 * 4] = pf[rep];
            __syncthreads();
            if (it + 1 < ntiles) {
                const float* kn = kbase + (size_t)(s0 + 64) * DD;
#pragma unroll
                for (int rep = 0; rep < 4; rep++)
                    pf[rep] = *(const float4*)&kn[(size_t)(prr + rep * 16) * DD + pc4 * 4];
            }

            float sc[8][4];
#pragma unroll
            for (int i = 0; i < 8; i++)
#pragma unroll
                for (int j = 0; j < 4; j++) sc[i][j] = 0.f;
#pragma unroll
            for (int d4 = 0; d4 < 16; d4++) {
                float4 kv[4];
#pragma unroll
                for (int j = 0; j < 4; j++)
                    kv[j] = *(const float4*)&kv_sm[tx * 4 + j][d4 * 4];
#pragma unroll
                for (int i = 0; i < 8; i++) {
                    float4 qv = *(const float4*)&q_sm[ty * 8 + i][d4 * 4];
#pragma unroll
                    for (int j = 0; j < 4; j++)
                        sc[i][j] += qv.x * kv[j].x + qv.y * kv[j].y +
                                    qv.z * kv[j].z + qv.w * kv[j].w;
                }
            }

#pragma unroll
            for (int i = 0; i < 8; i++) {
                const int row = ty * 8 + i;
                const int t = t0 + row;
#pragma unroll
                for (int j = 0; j < 4; j++) {
                    int s = s0 + tx * 4 + j;
                    sc[i][j] = (s <= t) ? sc[i][j] * 0.125f : -1e30f;
                }
                float tm = fmaxf(fmaxf(sc[i][0], sc[i][1]),
                                 fmaxf(sc[i][2], sc[i][3]));
#pragma unroll
                for (int off = 1; off < 16; off <<= 1)
                    tm = fmaxf(tm, __shfl_xor_sync(0xffffffffu, tm, off));
                float mn = fmaxf(m[i], tm);
                float ev[4], ls = 0.f;
#pragma unroll
                for (int j = 0; j < 4; j++) {
                    ev[j] = __expf(sc[i][j] - mn);
                    ls += ev[j];
                }
#pragma unroll
                for (int off = 1; off < 16; off <<= 1)
                    ls += __shfl_xor_sync(0xffffffffu, ls, off);
                l[i] = l[i] * __expf(m[i] - mn) + ls;
                m[i] = mn;
                if (tx == 0) mh[row][it] = mn;
                float* erow = g_e + ((size_t)(bh * TT + t)) * TT;
                *(float4*)&erow[s0 + tx * 4] = make_float4(ev[0], ev[1], ev[2], ev[3]);
            }
            __syncthreads();
        }

#pragma unroll
        for (int i = 0; i < 8; i++) {
            const float inv_l = 1.0f / l[i];
            for (int it = tx; it < ntiles; it += 16)
                mh[ty * 8 + i][it] = __expf(mh[ty * 8 + i][it] - m[i]) * inv_l;
        }
        __syncthreads();

        // ------------- Pass 2: sparsify, split, AV via HMMA -------------
        float acc[2][4][4];
#pragma unroll
        for (int mi = 0; mi < 2; mi++)
#pragma unroll
            for (int ni = 0; ni < 4; ni++)
#pragma unroll
                for (int r = 0; r < 4; r++) acc[mi][ni][r] = 0.f;

        // prefetch vt tile 0 (1024 x 16B chunks: h then l), 4 per thread
        uint4 pv[4];
#pragma unroll
        for (int rep = 0; rep < 4; rep++) {
            int c = rep * 256 + tid;
            int arr = c >> 9, cc = c & 511, d = cc >> 3, j = cc & 7;
            const __nv_bfloat16* src =
                (arr ? g_vtl : g_vth) + ((size_t)bh * DD + d) * TT + j * 8;
            pv[rep] = *(const uint4*)src;
        }

        for (int it = 0; it < ntiles; it++) {
            const int s0 = it * 64;
            // store vt tile
#pragma unroll
            for (int rep = 0; rep < 4; rep++) {
                int c = rep * 256 + tid;
                int arr = c >> 9, cc = c & 511, d = cc >> 3, j = cc & 7;
                __nv_bfloat16* dstp = (arr ? vt_sml : vt_smh) + d * 72 + j * 8;
                *(uint4*)dstp = pv[rep];
            }
            // sparsify + split a into bf16 hi/lo
#pragma unroll
            for (int i = 0; i < 8; i++) {
                const int row = ty * 8 + i;
                const int t = t0 + row;
                const float fac = mh[row][it];
                const float* erow = g_e + ((size_t)(bh * TT + t)) * TT;
                float4 ev = *(const float4*)&erow[s0 + tx * 4];
                uint32_t word = g_mask[((size_t)(bh * TT + t)) * (TT / 32) +
                                       (s0 >> 5) + (tx >> 3)];
                int bp = (tx & 7) * 4;
                float a0 = ev.x * fac, a1 = ev.y * fac,
                      a2 = ev.z * fac, a3 = ev.w * fac;
                a0 = (a0 > 0.01f || ((word >> (bp + 0)) & 1u)) ? a0 : 0.f;
                a1 = (a1 > 0.01f || ((word >> (bp + 1)) & 1u)) ? a1 : 0.f;
                a2 = (a2 > 0.01f || ((word >> (bp + 2)) & 1u)) ? a2 : 0.f;
                a3 = (a3 > 0.01f || ((word >> (bp + 3)) & 1u)) ? a3 : 0.f;
                __nv_bfloat16 h0 = __float2bfloat16(a0), h1 = __float2bfloat16(a1);
                __nv_bfloat16 h2 = __float2bfloat16(a2), h3 = __float2bfloat16(a3);
                __nv_bfloat16 l0 = __float2bfloat16(a0 - __bfloat162float(h0));
                __nv_bfloat16 l1 = __float2bfloat16(a1 - __bfloat162float(h1));
                __nv_bfloat16 l2 = __float2bfloat16(a2 - __bfloat162float(h2));
                __nv_bfloat16 l3 = __float2bfloat16(a3 - __bfloat162float(h3));
                uint32_t idx = row * 36 + tx * 2;
                ((uint32_t*)a_smh)[idx]     = pk(h0, h1);
                ((uint32_t*)a_smh)[idx + 1] = pk(h2, h3);
                ((uint32_t*)a_sml)[idx]     = pk(l0, l1);
                ((uint32_t*)a_sml)[idx + 1] = pk(l2, l3);
            }
            __syncthreads();

            if (it + 1 < ntiles) {
#pragma unroll
                for (int rep = 0; rep < 4; rep++) {
                    int c = rep * 256 + tid;
                    int arr = c >> 9, cc = c & 511, d = cc >> 3, j = cc & 7;
                    const __nv_bfloat16* src = (arr ? g_vtl : g_vth) +
                        ((size_t)bh * DD + d) * TT + s0 + 64 + j * 8;
                    pv[rep] = *(const uint4*)src;
                }
            }

            // AV MMA: warp tile 32(m) x 32(n), K=64 in 4 k16 steps
            const uint32_t* ah32 = (const uint32_t*)a_smh;
            const uint32_t* al32 = (const uint32_t*)a_sml;
            const uint32_t* vh32 = (const uint32_t*)vt_smh;
            const uint32_t* vl32 = (const uint32_t*)vt_sml;
#pragma unroll
            for (int ks = 0; ks < 4; ks++) {
                uint32_t ah[2][4], al[2][4], bh[4][2], bl[4][2];
#pragma unroll
                for (int mi = 0; mi < 2; mi++) {
                    int base = (wm * 32 + mi * 16 + g) * 36 + ks * 8 + (lane & 3);
                    ah[mi][0] = ah32[base];
                    ah[mi][1] = ah32[base + 8 * 36];
                    ah[mi][2] = ah32[base + 4];
                    ah[mi][3] = ah32[base + 8 * 36 + 4];
                    al[mi][0] = al32[base];
                    al[mi][1] = al32[base + 8 * 36];
                    al[mi][2] = al32[base + 4];
                    al[mi][3] = al32[base + 8 * 36 + 4];
                }
#pragma unroll
                for (int ni = 0; ni < 4; ni++) {
                    int base = (wn * 32 + ni * 8 + g) * 36 + ks * 8 + (lane & 3);
                    bh[ni][0] = vh32[base];
                    bh[ni][1] = vh32[base + 4];
                    bl[ni][0] = vl32[base];
                    bl[ni][1] = vl32[base + 4];
                }
#pragma unroll
                for (int mi = 0; mi < 2; mi++)
#pragma unroll
                    for (int ni = 0; ni < 4; ni++) {
                        mma16816(acc[mi][ni], ah[mi], bh[ni]);
                        mma16816(acc[mi][ni], ah[mi], bl[ni]);
                        mma16816(acc[mi][ni], al[mi], bh[ni]);
                    }
            }
            __syncthreads();
        }

        // epilogue: split output, write g_aoh/g_aol directly
        const int b = blockIdx.z, h = blockIdx.y;
#pragma unroll
        for (int mi = 0; mi < 2; mi++) {
#pragma unroll
            for (int ni = 0; ni < 4; ni++) {
                int mrow = wm * 32 + mi * 16 + g;
                int n = wn * 32 + ni * 8 + j2;
#pragma unroll
                for (int rr = 0; rr < 2; rr++) {
                    int t = t0 + mrow + rr * 8;
                    float v0 = acc[mi][ni][rr * 2 + 0];
                    float v1 = acc[mi][ni][rr * 2 + 1];
                    __nv_bfloat16 h0 = __float2bfloat16(v0);
                    __nv_bfloat16 h1 = __float2bfloat16(v1);
                    __nv_bfloat16 l0 = __float2bfloat16(v0 - __bfloat162float(h0));
                    __nv_bfloat16 l1 = __float2bfloat16(v1 - __bfloat162float(h1));
                    size_t o = ((size_t)(b * TT + t) * CC + h * 64 + n) >> 1;
                    ((uint32_t*)g_aoh)[o] = pk(h0, h1);
                    ((uint32_t*)g_aol)[o] = pk(l0, l1);
                }
            }
        }
        __syncthreads();
    }
}

// ---------------------------------------------------------------------------
extern "C" void kernel_launch(void* const* d_in, const int* in_sizes, int n_in,
                              void* d_out, int out_size) {
    const float* x    = (const float*)d_in[0];
    const float* Wqkv = (const float*)d_in[1];
    const float* bqkv = (const float*)d_in[2];
    const float* Wout = (const float*)d_in[3];
    const float* bout = (const float*)d_in[4];
    float* out = (float*)d_out;

    cudaFuncSetAttribute(attn_kernel,
                         cudaFuncAttributeMaxDynamicSharedMemorySize, ATTN_SMEM);
    cudaFuncSetAttribute(hmma_gemm,
                         cudaFuncAttributeMaxDynamicSharedMemorySize, GEMM_SMEM);

    // 0) Regrow bitmask (input-independent)
    mask_kernel<<<dim3(8, TT, BB * HH), 256>>>();

    // 1) Split-bf16 conversions: x -> g_xh/g_xl, Wqkv^T, Wout^T
    conv_rows<<<(BB * TT * CC / 4 + 255) / 256, 256>>>(x, BB * TT * CC / 4);
    conv_tr<<<dim3(3 * CC / 32, CC / 32), dim3(32, 8)>>>(Wqkv, CC, 3 * CC, 0);
    conv_tr<<<dim3(CC / 32, CC / 32), dim3(32, 8)>>>(Wout, CC, CC, 1);

    // 2) QKV projection (HMMA split-bf16), scattered to q/k/v
    hmma_gemm<<<dim3(3 * CC / 128, BB * TT / 128), 256, GEMM_SMEM>>>(
        bqkv, nullptr, 0);

    // 2b) V -> V^T bf16 hi/lo
    vt_split<<<dim3(DD / 32, TT / 32, BB * HH), dim3(32, 8)>>>();

    // 3) Attention (pass1 fp32, pass2 HMMA AV) -> writes g_aoh/g_aol
    attn_kernel<<<dim3(TT / 256, HH, BB), 256, ATTN_SMEM>>>();

    // 4) Output projection (HMMA split-bf16)
    hmma_gemm<<<dim3(CC / 128, BB * TT / 128), 256, GEMM_SMEM>>>(
        bout, out, 1);
}

// round 10
// speedup vs baseline: 1.9292x; 1.1687x over previous
#include <cuda_runtime.h>
#include <cuda_bf16.h>
#include <stdint.h>

#define BB 2
#define TT 2048
#define CC 1024
#define HH 16
#define DD 64

// ---------------------------------------------------------------------------
// Scratch (allocation-free rule: __device__ globals). Device-code refs only.
// ---------------------------------------------------------------------------
__device__ float g_v[BB * HH * TT * DD];
__device__ float g_e[(size_t)BB * HH * TT * TT];
__device__ uint32_t g_mask[(size_t)BB * HH * TT * (TT / 32)];
// q, k in 3-way bf16 decomposition (h + m + l ~ fp32): [bh][t][d]
__device__ __nv_bfloat16 g_qh[BB * HH * TT * DD], g_qm[BB * HH * TT * DD],
                         g_ql[BB * HH * TT * DD];
__device__ __nv_bfloat16 g_kh[BB * HH * TT * DD], g_km[BB * HH * TT * DD],
                         g_kl[BB * HH * TT * DD];
// split-bf16 GEMM operands
__device__ __nv_bfloat16 g_xh[BB * TT * CC], g_xl[BB * TT * CC];
__device__ __nv_bfloat16 g_wqh[3 * CC * CC], g_wql[3 * CC * CC];
__device__ __nv_bfloat16 g_woh[CC * CC], g_wol[CC * CC];
__device__ __nv_bfloat16 g_aoh[BB * TT * CC], g_aol[BB * TT * CC];
// V transposed per (b,h): [bh][d][t], bf16 hi/lo
__device__ __nv_bfloat16 g_vth[(size_t)BB * HH * DD * TT];
__device__ __nv_bfloat16 g_vtl[(size_t)BB * HH * DD * TT];

// ---------------------------------------------------------------------------
// sm_80-level PTX helpers
// ---------------------------------------------------------------------------
__device__ __forceinline__ uint32_t smem_u32(const void* p) {
    uint32_t a;
    asm("{ .reg .u64 t; cvta.to.shared.u64 t, %1; cvt.u32.u64 %0, t; }"
        : "=r"(a) : "l"(p));
    return a;
}
__device__ __forceinline__ void cp16(uint32_t dst, const void* src) {
    asm volatile("cp.async.cg.shared.global [%0], [%1], 16;"
                 :: "r"(dst), "l"(src) : "memory");
}
#define CP_COMMIT() asm volatile("cp.async.commit_group;" ::: "memory")
#define CP_WAIT(n)  asm volatile("cp.async.wait_group %0;" :: "n"(n) : "memory")

__device__ __forceinline__ void mma16816(float* c, const uint32_t* a,
                                         const uint32_t* b) {
    asm volatile(
        "mma.sync.aligned.m16n8k16.row.col.f32.bf16.bf16.f32 "
        "{%0,%1,%2,%3},{%4,%5,%6,%7},{%8,%9},{%0,%1,%2,%3};"
        : "+f"(c[0]), "+f"(c[1]), "+f"(c[2]), "+f"(c[3])
        : "r"(a[0]), "r"(a[1]), "r"(a[2]), "r"(a[3]), "r"(b[0]), "r"(b[1]));
}
__device__ __forceinline__ uint32_t pk(__nv_bfloat16 a, __nv_bfloat16 b) {
    return (uint32_t)__bfloat16_as_ushort(a) |
           ((uint32_t)__bfloat16_as_ushort(b) << 16);
}
__device__ __forceinline__ void split3(float v, __nv_bfloat16& h,
                                       __nv_bfloat16& m, __nv_bfloat16& l) {
    h = __float2bfloat16(v);
    float r = v - __bfloat162float(h);
    m = __float2bfloat16(r);
    l = __float2bfloat16(r - __bfloat162float(m));
}

// ---------------------------------------------------------------------------
// Threefry-2x32, key = (0, 42)
// ---------------------------------------------------------------------------
__device__ __forceinline__ uint2 threefry_0_42(uint32_t x0, uint32_t x1) {
    const uint32_t ks0 = 0u, ks1 = 42u;
    const uint32_t ks2 = 0x1BD11BDAu ^ ks0 ^ ks1;
    x0 += ks0; x1 += ks1;
#define TF_RND(rot) { x0 += x1; x1 = __funnelshift_l(x1, x1, (rot)); x1 ^= x0; }
    TF_RND(13) TF_RND(15) TF_RND(26) TF_RND(6)
    x0 += ks1; x1 += ks2 + 1u;
    TF_RND(17) TF_RND(29) TF_RND(16) TF_RND(24)
    x0 += ks2; x1 += ks0 + 2u;
    TF_RND(13) TF_RND(15) TF_RND(26) TF_RND(6)
    x0 += ks0; x1 += ks1 + 3u;
    TF_RND(17) TF_RND(29) TF_RND(16) TF_RND(24)
    x0 += ks1; x1 += ks2 + 4u;
    TF_RND(13) TF_RND(15) TF_RND(26) TF_RND(6)
    x0 += ks2; x1 += ks0 + 5u;
#undef TF_RND
    return make_uint2(x0, x1);
}
__device__ __forceinline__ bool regrow_test(uint32_t idx) {
    uint2 rb = threefry_0_42(0u, idx);
    return ((rb.x ^ rb.y) >> 9) <= 419430u;
}

__global__ void __launch_bounds__(256)
mask_kernel() {
    const int t  = blockIdx.y;
    const int bh = blockIdx.z;
    const int w  = blockIdx.x * 8 + (threadIdx.x >> 5);
    if (w * 32 > t) return;
    const int lane = threadIdx.x & 31;
    const uint32_t s = (uint32_t)(w * 32 + lane);
    const uint32_t idx = ((uint32_t)(bh * TT + t)) * (uint32_t)TT + s;
    uint32_t word = __ballot_sync(0xffffffffu, regrow_test(idx));
    if (lane == 0) g_mask[((size_t)(bh * TT + t)) * (TT / 32) + w] = word;
}

// ---------------------------------------------------------------------------
// fp32 -> bf16 hi/lo split: x -> g_xh/g_xl
// ---------------------------------------------------------------------------
__global__ void __launch_bounds__(256)
conv_rows(const float* __restrict__ X, int n4) {
    int i = blockIdx.x * 256 + threadIdx.x;
    if (i >= n4) return;
    float4 v = ((const float4*)X)[i];
    float vv[4] = {v.x, v.y, v.z, v.w};
    __nv_bfloat16 h[4], l[4];
#pragma unroll
    for (int j = 0; j < 4; j++) {
        h[j] = __float2bfloat16(vv[j]);
        l[j] = __float2bfloat16(vv[j] - __bfloat162float(h[j]));
    }
    ((uint32_t*)g_xh)[i * 2]     = pk(h[0], h[1]);
    ((uint32_t*)g_xh)[i * 2 + 1] = pk(h[2], h[3]);
    ((uint32_t*)g_xl)[i * 2]     = pk(l[0], l[1]);
    ((uint32_t*)g_xl)[i * 2 + 1] = pk(l[2], l[3]);
}

// W [K][N] fp32 -> W^T [N][K] bf16 hi/lo.  sel 0: g_wqh/g_wql, 1: g_woh/g_wol
__global__ void __launch_bounds__(256)
conv_tr(const float* __restrict__ W, int K, int N, int sel) {
    __shared__ float sm[32][33];
    __nv_bfloat16* Th = (sel == 0) ? g_wqh : g_woh;
    __nv_bfloat16* Tl = (sel == 0) ? g_wql : g_wol;
    const int n0 = blockIdx.x * 32, k0 = blockIdx.y * 32;
    const int tx = threadIdx.x, ty = threadIdx.y;
#pragma unroll
    for (int i = 0; i < 4; i++)
        sm[ty + i * 8][tx] = W[(size_t)(k0 + ty + i * 8) * N + n0 + tx];
    __syncthreads();
#pragma unroll
    for (int i = 0; i < 4; i++) {
        float v = sm[tx][ty + i * 8];
        __nv_bfloat16 h = __float2bfloat16(v);
        __nv_bfloat16 l = __float2bfloat16(v - __bfloat162float(h));
        size_t o = (size_t)(n0 + ty + i * 8) * K + k0 + tx;
        Th[o] = h; Tl[o] = l;
    }
}

// g_v [bh][t][d] fp32 -> g_vth/g_vtl [bh][d][t] bf16 hi/lo
__global__ void __launch_bounds__(256)
vt_split() {
    __shared__ float sm[32][33];
    const int bh = blockIdx.z;
    const int d0 = blockIdx.x * 32;
    const int t0 = blockIdx.y * 32;
    const int tx = threadIdx.x, ty = threadIdx.y;
    const float* src = g_v + (size_t)bh * TT * DD;
#pragma unroll
    for (int i = 0; i < 4; i++)
        sm[ty + i * 8][tx] = src[(size_t)(t0 + ty + i * 8) * DD + d0 + tx];
    __syncthreads();
#pragma unroll
    for (int i = 0; i < 4; i++) {
        float v = sm[tx][ty + i * 8];
        __nv_bfloat16 h = __float2bfloat16(v);
        __nv_bfloat16 l = __float2bfloat16(v - __bfloat162float(h));
        size_t o = ((size_t)bh * DD + d0 + ty + i * 8) * TT + t0 + tx;
        g_vth[o] = h; g_vtl[o] = l;
    }
}

// ---------------------------------------------------------------------------
// Split-bf16 HMMA GEMM (verified): C = A @ Bt^T + bias.
//   sel 0: A=g_xh/g_xl, Bt=g_wqh/g_wql; scatter q,k as 3-way bf16, v fp32.
//   sel 1: A=g_aoh/g_aol, Bt=g_woh/g_wol; row-major store to Cout.
// ---------------------------------------------------------------------------
#define GOPE   (128 * 40)
#define GSTAGE (4 * GOPE)
#define GEMM_SMEM (2 * GSTAGE * 2)

__global__ void __launch_bounds__(256)
hmma_gemm(const float* __restrict__ bias, float* __restrict__ Cout, int sel) {
    extern __shared__ __nv_bfloat16 gsm[];
    const __nv_bfloat16* Ah = (sel == 0) ? g_xh : g_aoh;
    const __nv_bfloat16* Al = (sel == 0) ? g_xl : g_aol;
    const __nv_bfloat16* Bh = (sel == 0) ? g_wqh : g_woh;
    const __nv_bfloat16* Bl = (sel == 0) ? g_wql : g_wol;
    const int Kdim = CC;
    const int Ncols = (sel == 0) ? 3 * CC : CC;

    const int tid = threadIdx.x;
    const int lane = tid & 31, wid = tid >> 5;
    const int wm = wid & 3, wn = wid >> 2;
    const int n0 = blockIdx.x * 128, m0 = blockIdx.y * 128;
    const int g = lane >> 2, j2 = (lane & 3) * 2;

    float acc[2][8][4];
#pragma unroll
    for (int mi = 0; mi < 2; mi++)
#pragma unroll
        for (int ni = 0; ni < 8; ni++)
#pragma unroll
            for (int r = 0; r < 4; r++) acc[mi][ni][r] = 0.f;

    const int nch = Kdim / 32;

#define ISSUE_LOADS(IT, STAGE) do {                                          \
        const int _k0 = (IT) * 32;                                          \
        __nv_bfloat16* _sb = gsm + (STAGE) * GSTAGE;                         \
        _Pragma("unroll")                                                    \
        for (int _r = 0; _r < 2; _r++) {                                     \
            int _c = _r * 256 + tid;                                         \
            int _row = _c >> 2, _off = (_c & 3) * 8;                         \
            uint32_t _so = smem_u32(_sb + _row * 40 + _off);                 \
            size_t _ga = (size_t)(m0 + _row) * Kdim + _k0 + _off;            \
            size_t _gb = (size_t)(n0 + _row) * Kdim + _k0 + _off;            \
            cp16(_so,                 Ah + _ga);                             \
            cp16(_so + 2 * GOPE,      Al + _ga);                             \
            cp16(_so + 4 * GOPE,      Bh + _gb);                             \
            cp16(_so + 6 * GOPE,      Bl + _gb);                             \
        }                                                                    \
    } while (0)

    ISSUE_LOADS(0, 0);
    CP_COMMIT();

    for (int it = 0; it < nch; it++) {
        if (it + 1 < nch) {
            ISSUE_LOADS(it + 1, (it + 1) & 1);
            CP_COMMIT();
            CP_WAIT(1);
        } else {
            CP_WAIT(0);
        }
        __syncthreads();

        const __nv_bfloat16* sAh = gsm + (it & 1) * GSTAGE;
        const __nv_bfloat16* sAl = sAh + GOPE;
        const __nv_bfloat16* sBh = sAh + 2 * GOPE;
        const __nv_bfloat16* sBl = sAh + 3 * GOPE;

#pragma unroll
        for (int ks = 0; ks < 2; ks++) {
            const int k0 = ks * 16;
            uint32_t ah[2][4], al[2][4], bh[8][2], bl[8][2];
#pragma unroll
            for (int mi = 0; mi < 2; mi++) {
                int row = wm * 32 + mi * 16;
                ah[mi][0] = *(const uint32_t*)&sAh[(row + g) * 40 + k0 + j2];
                ah[mi][1] = *(const uint32_t*)&sAh[(row + 8 + g) * 40 + k0 + j2];
                ah[mi][2] = *(const uint32_t*)&sAh[(row + g) * 40 + k0 + j2 + 8];
                ah[mi][3] = *(const uint32_t*)&sAh[(row + 8 + g) * 40 + k0 + j2 + 8];
                al[mi][0] = *(const uint32_t*)&sAl[(row + g) * 40 + k0 + j2];
                al[mi][1] = *(const uint32_t*)&sAl[(row + 8 + g) * 40 + k0 + j2];
                al[mi][2] = *(const uint32_t*)&sAl[(row + g) * 40 + k0 + j2 + 8];
                al[mi][3] = *(const uint32_t*)&sAl[(row + 8 + g) * 40 + k0 + j2 + 8];
            }
#pragma unroll
            for (int ni = 0; ni < 8; ni++) {
                int n = wn * 64 + ni * 8 + g;
                bh[ni][0] = *(const uint32_t*)&sBh[n * 40 + k0 + j2];
                bh[ni][1] = *(const uint32_t*)&sBh[n * 40 + k0 + j2 + 8];
                bl[ni][0] = *(const uint32_t*)&sBl[n * 40 + k0 + j2];
                bl[ni][1] = *(const uint32_t*)&sBl[n * 40 + k0 + j2 + 8];
            }
#pragma unroll
            for (int mi = 0; mi < 2; mi++)
#pragma unroll
                for (int ni = 0; ni < 8; ni++) {
                    mma16816(acc[mi][ni], ah[mi], bh[ni]);
                    mma16816(acc[mi][ni], ah[mi], bl[ni]);
                    mma16816(acc[mi][ni], al[mi], bh[ni]);
                }
        }
        __syncthreads();
    }

#pragma unroll
    for (int mi = 0; mi < 2; mi++) {
#pragma unroll
        for (int ni = 0; ni < 8; ni++) {
            int m_r = m0 + wm * 32 + mi * 16 + g;
            int n_c = n0 + wn * 64 + ni * 8 + j2;
            float b0 = bias[n_c], b1 = bias[n_c + 1];
            float v00 = acc[mi][ni][0] + b0, v01 = acc[mi][ni][1] + b1;
            float v10 = acc[mi][ni][2] + b0, v11 = acc[mi][ni][3] + b1;
            if (sel == 1) {
                *(float2*)&Cout[(size_t)m_r * Ncols + n_c] = make_float2(v00, v01);
                *(float2*)&Cout[(size_t)(m_r + 8) * Ncols + n_c] = make_float2(v10, v11);
            } else {
                int part = n_c >> 10, rem = n_c & 1023;
                int hh = rem >> 6, dd = rem & 63;
                int b = m_r >> 11, t = m_r & 2047;
                int b2 = (m_r + 8) >> 11, t2 = (m_r + 8) & 2047;
                size_t o1 = (((size_t)b * HH + hh) * TT + t) * DD + dd;
                size_t o2 = (((size_t)b2 * HH + hh) * TT + t2) * DD + dd;
                if (part == 2) {
                    *(float2*)&g_v[o1] = make_float2(v00, v01);
                    *(float2*)&g_v[o2] = make_float2(v10, v11);
                } else {
                    __nv_bfloat16* AH = (part == 0) ? g_qh : g_kh;
                    __nv_bfloat16* AM = (part == 0) ? g_qm : g_km;
                    __nv_bfloat16* AL = (part == 0) ? g_ql : g_kl;
                    __nv_bfloat16 h0, mm0, l0, h1, mm1, l1;
                    split3(v00, h0, mm0, l0);
                    split3(v01, h1, mm1, l1);
                    ((uint32_t*)AH)[o1 >> 1] = pk(h0, h1);
                    ((uint32_t*)AM)[o1 >> 1] = pk(mm0, mm1);
                    ((uint32_t*)AL)[o1 >> 1] = pk(l0, l1);
                    split3(v10, h0, mm0, l0);
                    split3(v11, h1, mm1, l1);
                    ((uint32_t*)AH)[o2 >> 1] = pk(h0, h1);
                    ((uint32_t*)AM)[o2 >> 1] = pk(mm0, mm1);
                    ((uint32_t*)AL)[o2 >> 1] = pk(l0, l1);
                }
            }
        }
    }
#undef ISSUE_LOADS
}

// ---------------------------------------------------------------------------
// Attention. Pass 1: S = QK^T via 6-term 3-way-split bf16 HMMA (fp32-quality
// scores), S staged through smem, then the verified fp32 online-softmax /
// e-cache path unchanged. Pass 2: verbatim R9 (sparsify + AV HMMA).
// smem: mh 16KB | A 36KB (q-stage hi/mid -> S -> a_smh/l) | B 27KB
// (q-stage lo -> k3 tiles -> vt). 1 block/SM (high regs).
// ---------------------------------------------------------------------------
#define ATTN_SMEM 80896

__global__ void __launch_bounds__(256, 1)
attn_kernel() {
    extern __shared__ float asmem[];
    float (*mh)[32] = (float(*)[32])(asmem);
    __nv_bfloat16* qA = (__nv_bfloat16*)(asmem + 4096);    // A region
    __nv_bfloat16* qB = (__nv_bfloat16*)(asmem + 13312);   // B region
    float* S_f = asmem + 4096;                             // S (A region)
    __nv_bfloat16* a_smh  = (__nv_bfloat16*)(asmem + 4096);
    __nv_bfloat16* a_sml  = a_smh + 128 * 72;
    __nv_bfloat16* vt_smh = (__nv_bfloat16*)(asmem + 13312);
    __nv_bfloat16* vt_sml = vt_smh + 64 * 72;

    const int NQB = TT / 128;
    const int bh = blockIdx.z * HH + blockIdx.y;
    const int tid = threadIdx.x;
    const int ty = tid >> 4;
    const int tx = tid & 15;
    const int lane = tid & 31, wid = tid >> 5;
    const int wm = wid & 3, wn = wid >> 2;
    const int g = lane >> 2, qd = lane & 3, j2 = qd * 2;

    const uint32_t* qh32 = (const uint32_t*)qA;
    const uint32_t* qm32 = qh32 + 4608;
    const uint32_t* ql32 = (const uint32_t*)qB;
    const uint32_t* kh32s = (const uint32_t*)qB;
    const uint32_t* km32s = kh32s + 2304;
    const uint32_t* kl32s = kh32s + 4608;

    for (int half = 0; half < 2; half++) {
        const int qb = half == 0 ? (NQB - 1 - (int)blockIdx.x) : (int)blockIdx.x;
        const int t0 = qb * 128;
        const int ntiles = 2 * qb + 2;

        // ---- stage q3 tile (128 x 64 x {h,m,l}) into smem ----
#pragma unroll
        for (int rep = 0; rep < 12; rep++) {
            int c = rep * 256 + tid;
            int arr = c >> 10, cc = c & 1023, row = cc >> 3, j = cc & 7;
            const __nv_bfloat16* src =
                (arr == 0 ? g_qh : arr == 1 ? g_qm : g_ql) +
                ((size_t)bh * TT + t0 + row) * DD + j * 8;
            __nv_bfloat16* dst =
                (arr == 0 ? qA : arr == 1 ? qA + 9216 : qB) + row * 72 + j * 8;
            *(uint4*)dst = *(const uint4*)src;
        }
        __syncthreads();

        // ---- build Q fragments (held in registers for all tiles) ----
        uint32_t qfh[4][4], qfm[4][4], qfl[4][4];
#pragma unroll
        for (int ks = 0; ks < 4; ks++) {
            int b0 = (16 * wid + g) * 36 + ks * 8 + qd;
            int b1 = b0 + 8 * 36;
            qfh[ks][0] = qh32[b0]; qfh[ks][1] = qh32[b1];
            qfh[ks][2] = qh32[b0 + 4]; qfh[ks][3] = qh32[b1 + 4];
            qfm[ks][0] = qm32[b0]; qfm[ks][1] = qm32[b1];
            qfm[ks][2] = qm32[b0 + 4]; qfm[ks][3] = qm32[b1 + 4];
            qfl[ks][0] = ql32[b0]; qfl[ks][1] = ql32[b1];
            qfl[ks][2] = ql32[b0 + 4]; qfl[ks][3] = ql32[b1 + 4];
        }
        __syncthreads();

        float m[8], l[8];
#pragma unroll
        for (int i = 0; i < 8; i++) { m[i] = -1e30f; l[i] = 0.f; }

        // prefetch k3 tile 0: 1536 x 16B chunks, 6 per thread
        uint4 pf6[6];
#pragma unroll
        for (int rep = 0; rep < 6; rep++) {
            int c = rep * 256 + tid;
            int arr = c >> 9, cc = c & 511, row = cc >> 3, j = cc & 7;
            const __nv_bfloat16* src =
                (arr == 0 ? g_kh : arr == 1 ? g_km : g_kl) +
                ((size_t)bh * TT + row) * DD + j * 8;
            pf6[rep] = *(const uint4*)src;
        }

        // ---------------- Pass 1 ----------------
        for (int it = 0; it < ntiles; it++) {
            const int s0 = it * 64;
#pragma unroll
            for (int rep = 0; rep < 6; rep++) {
                int c = rep * 256 + tid;
                int arr = c >> 9, cc = c & 511, row = cc >> 3, j = cc & 7;
                *(uint4*)(qB + arr * 4608 + row * 72 + j * 8) = pf6[rep];
            }
            __syncthreads();

            if (it + 1 < ntiles) {
#pragma unroll
                for (int rep = 0; rep < 6; rep++) {
                    int c = rep * 256 + tid;
                    int arr = c >> 9, cc = c & 511, row = cc >> 3, j = cc & 7;
                    const __nv_bfloat16* src =
                        (arr == 0 ? g_kh : arr == 1 ? g_km : g_kl) +
                        ((size_t)bh * TT + s0 + 64 + row) * DD + j * 8;
                    pf6[rep] = *(const uint4*)src;
                }
            }

            // S = Q K^T  (6-term split)
            float acc[8][4];
#pragma unroll
            for (int ni = 0; ni < 8; ni++)
#pragma unroll
                for (int r = 0; r < 4; r++) acc[ni][r] = 0.f;

#pragma unroll
            for (int ks = 0; ks < 4; ks++) {
#pragma unroll
                for (int ni = 0; ni < 8; ni++) {
                    int bb = (ni * 8 + g) * 36 + ks * 8 + qd;
                    uint32_t b_h[2] = {kh32s[bb], kh32s[bb + 4]};
                    uint32_t b_m[2] = {km32s[bb], km32s[bb + 4]};
                    uint32_t b_l[2] = {kl32s[bb], kl32s[bb + 4]};
                    mma16816(acc[ni], qfh[ks], b_h);
                    mma16816(acc[ni], qfm[ks], b_h);
                    mma16816(acc[ni], qfl[ks], b_h);
                    mma16816(acc[ni], qfh[ks], b_m);
                    mma16816(acc[ni], qfm[ks], b_m);
                    mma16816(acc[ni], qfh[ks], b_l);
                }
            }
            // store S (verified c-fragment map)
#pragma unroll
            for (int ni = 0; ni < 8; ni++) {
                *(float2*)&S_f[(16 * wid + g) * 72 + ni * 8 + j2] =
                    make_float2(acc[ni][0], acc[ni][1]);
                *(float2*)&S_f[(16 * wid + 8 + g) * 72 + ni * 8 + j2] =
                    make_float2(acc[ni][2], acc[ni][3]);
            }
            __syncthreads();

            // ---- verified softmax / e-cache path (reads S from smem) ----
            float sc[8][4];
#pragma unroll
            for (int i = 0; i < 8; i++)
                *(float4*)&sc[i][0] =
                    *(const float4*)&S_f[(ty * 8 + i) * 72 + tx * 4];

#pragma unroll
            for (int i = 0; i < 8; i++) {
                const int row = ty * 8 + i;
                const int t = t0 + row;
#pragma unroll
                for (int j = 0; j < 4; j++) {
                    int s = s0 + tx * 4 + j;
                    sc[i][j] = (s <= t) ? sc[i][j] * 0.125f : -1e30f;
                }
                float tm = fmaxf(fmaxf(sc[i][0], sc[i][1]),
                                 fmaxf(sc[i][2], sc[i][3]));
#pragma unroll
                for (int off = 1; off < 16; off <<= 1)
                    tm = fmaxf(tm, __shfl_xor_sync(0xffffffffu, tm, off));
                float mn = fmaxf(m[i], tm);
                float ev[4], ls = 0.f;
#pragma unroll
                for (int j = 0; j < 4; j++) {
                    ev[j] = __expf(sc[i][j] - mn);
                    ls += ev[j];
                }
#pragma unroll
                for (int off = 1; off < 16; off <<= 1)
                    ls += __shfl_xor_sync(0xffffffffu, ls, off);
                l[i] = l[i] * __expf(m[i] - mn) + ls;
                m[i] = mn;
                if (tx == 0) mh[row][it] = mn;
                float* erow = g_e + ((size_t)(bh * TT + t)) * TT;
                *(float4*)&erow[s0 + tx * 4] =
                    make_float4(ev[0], ev[1], ev[2], ev[3]);
            }
        }
        __syncthreads();

#pragma unroll
        for (int i = 0; i < 8; i++) {
            const float inv_l = 1.0f / l[i];
            for (int it = tx; it < ntiles; it += 16)
                mh[ty * 8 + i][it] = __expf(mh[ty * 8 + i][it] - m[i]) * inv_l;
        }
        __syncthreads();

        // ---------------- Pass 2 (verbatim R9) ----------------
        float acc2[2][4][4];
#pragma unroll
        for (int mi = 0; mi < 2; mi++)
#pragma unroll
            for (int ni = 0; ni < 4; ni++)
#pragma unroll
                for (int r = 0; r < 4; r++) acc2[mi][ni][r] = 0.f;

        uint4 pv[4];
#pragma unroll
        for (int rep = 0; rep < 4; rep++) {
            int c = rep * 256 + tid;
            int arr = c >> 9, cc = c & 511, d = cc >> 3, j = cc & 7;
            const __nv_bfloat16* src =
                (arr ? g_vtl : g_vth) + ((size_t)bh * DD + d) * TT + j * 8;
            pv[rep] = *(const uint4*)src;
        }

        for (int it = 0; it < ntiles; it++) {
            const int s0 = it * 64;
#pragma unroll
            for (int rep = 0; rep < 4; rep++) {
                int c = rep * 256 + tid;
                int arr = c >> 9, cc = c & 511, d = cc >> 3, j = cc & 7;
                __nv_bfloat16* dstp = (arr ? vt_sml : vt_smh) + d * 72 + j * 8;
                *(uint4*)dstp = pv[rep];
            }
#pragma unroll
            for (int i = 0; i < 8; i++) {
                const int row = ty * 8 + i;
                const int t = t0 + row;
                const float fac = mh[row][it];
                const float* erow = g_e + ((size_t)(bh * TT + t)) * TT;
                float4 ev = *(const float4*)&erow[s0 + tx * 4];
                uint32_t word = g_mask[((size_t)(bh * TT + t)) * (TT / 32) +
                                       (s0 >> 5) + (tx >> 3)];
                int bp = (tx & 7) * 4;
                float a0 = ev.x * fac, a1 = ev.y * fac,
                      a2 = ev.z * fac, a3 = ev.w * fac;
                a0 = (a0 > 0.01f || ((word >> (bp + 0)) & 1u)) ? a0 : 0.f;
                a1 = (a1 > 0.01f || ((word >> (bp + 1)) & 1u)) ? a1 : 0.f;
                a2 = (a2 > 0.01f || ((word >> (bp + 2)) & 1u)) ? a2 : 0.f;
                a3 = (a3 > 0.01f || ((word >> (bp + 3)) & 1u)) ? a3 : 0.f;
                __nv_bfloat16 h0 = __float2bfloat16(a0), h1 = __float2bfloat16(a1);
                __nv_bfloat16 h2 = __float2bfloat16(a2), h3 = __float2bfloat16(a3);
                __nv_bfloat16 l0 = __float2bfloat16(a0 - __bfloat162float(h0));
                __nv_bfloat16 l1 = __float2bfloat16(a1 - __bfloat162float(h1));
                __nv_bfloat16 l2 = __float2bfloat16(a2 - __bfloat162float(h2));
                __nv_bfloat16 l3 = __float2bfloat16(a3 - __bfloat162float(h3));
                uint32_t idx = row * 36 + tx * 2;
                ((uint32_t*)a_smh)[idx]     = pk(h0, h1);
                ((uint32_t*)a_smh)[idx + 1] = pk(h2, h3);
                ((uint32_t*)a_sml)[idx]     = pk(l0, l1);
                ((uint32_t*)a_sml)[idx + 1] = pk(l2, l3);
            }
            __syncthreads();

            if (it + 1 < ntiles) {
#pragma unroll
                for (int rep = 0; rep < 4; rep++) {
                    int c = rep * 256 + tid;
                    int arr = c >> 9, cc = c & 511, d = cc >> 3, j = cc & 7;
                    const __nv_bfloat16* src = (arr ? g_vtl : g_vth) +
                        ((size_t)bh * DD + d) * TT + s0 + 64 + j * 8;
                    pv[rep] = *(const uint4*)src;
                }
            }

            const uint32_t* ah32 = (const uint32_t*)a_smh;
            const uint32_t* al32 = (const uint32_t*)a_sml;
            const uint32_t* vh32 = (const uint32_t*)vt_smh;
            const uint32_t* vl32 = (const uint32_t*)vt_sml;
#pragma unroll
            for (int ks = 0; ks < 4; ks++) {
                uint32_t ah[2][4], al[2][4], bh[4][2], bl[4][2];
#pragma unroll
                for (int mi = 0; mi < 2; mi++) {
                    int base = (wm * 32 + mi * 16 + g) * 36 + ks * 8 + qd;
                    ah[mi][0] = ah32[base];
                    ah[mi][1] = ah32[base + 8 * 36];
                    ah[mi][2] = ah32[base + 4];
                    ah[mi][3] = ah32[base + 8 * 36 + 4];
                    al[mi][0] = al32[base];
                    al[mi][1] = al32[base + 8 * 36];
                    al[mi][2] = al32[base + 4];
                    al[mi][3] = al32[base + 8 * 36 + 4];
                }
#pragma unroll
                for (int ni = 0; ni < 4; ni++) {
                    int base = (wn * 32 + ni * 8 + g) * 36 + ks * 8 + qd;
                    bh[ni][0] = vh32[base];
                    bh[ni][1] = vh32[base + 4];
                    bl[ni][0] = vl32[base];
                    bl[ni][1] = vl32[base + 4];
                }
#pragma unroll
                for (int mi = 0; mi < 2; mi++)
#pragma unroll
                    for (int ni = 0; ni < 4; ni++) {
                        mma16816(acc2[mi][ni], ah[mi], bh[ni]);
                        mma16816(acc2[mi][ni], ah[mi], bl[ni]);
                        mma16816(acc2[mi][ni], al[mi], bh[ni]);
                    }
            }
            __syncthreads();
        }

        const int b = blockIdx.z, h = blockIdx.y;
#pragma unroll
        for (int mi = 0; mi < 2; mi++) {
#pragma unroll
            for (int ni = 0; ni < 4; ni++) {
                int mrow = wm * 32 + mi * 16 + g;
                int n = wn * 32 + ni * 8 + j2;
#pragma unroll
                for (int rr = 0; rr < 2; rr++) {
                    int t = t0 + mrow + rr * 8;
                    float v0 = acc2[mi][ni][rr * 2 + 0];
                    float v1 = acc2[mi][ni][rr * 2 + 1];
                    __nv_bfloat16 h0 = __float2bfloat16(v0);
                    __nv_bfloat16 h1 = __float2bfloat16(v1);
                    __nv_bfloat16 l0 = __float2bfloat16(v0 - __bfloat162float(h0));
                    __nv_bfloat16 l1 = __float2bfloat16(v1 - __bfloat162float(h1));
                    size_t o = ((size_t)(b * TT + t) * CC + h * 64 + n) >> 1;
                    ((uint32_t*)g_aoh)[o] = pk(h0, h1);
                    ((uint32_t*)g_aol)[o] = pk(l0, l1);
                }
            }
        }
        __syncthreads();
    }
}

// ---------------------------------------------------------------------------
extern "C" void kernel_launch(void* const* d_in, const int* in_sizes, int n_in,
                              void* d_out, int out_size) {
    const float* x    = (const float*)d_in[0];
    const float* Wqkv = (const float*)d_in[1];
    const float* bqkv = (const float*)d_in[2];
    const float* Wout = (const float*)d_in[3];
    const float* bout = (const float*)d_in[4];
    float* out = (float*)d_out;

    cudaFuncSetAttribute(attn_kernel,
                         cudaFuncAttributeMaxDynamicSharedMemorySize, ATTN_SMEM);
    cudaFuncSetAttribute(hmma_gemm,
                         cudaFuncAttributeMaxDynamicSharedMemorySize, GEMM_SMEM);

    // 0) Regrow bitmask (input-independent)
    mask_kernel<<<dim3(8, TT, BB * HH), 256>>>();

    // 1) Split-bf16 conversions
    conv_rows<<<(BB * TT * CC / 4 + 255) / 256, 256>>>(x, BB * TT * CC / 4);
    conv_tr<<<dim3(3 * CC / 32, CC / 32), dim3(32, 8)>>>(Wqkv, CC, 3 * CC, 0);
    conv_tr<<<dim3(CC / 32, CC / 32), dim3(32, 8)>>>(Wout, CC, CC, 1);

    // 2) QKV projection -> q,k (3-way bf16), v (fp32)
    hmma_gemm<<<dim3(3 * CC / 128, BB * TT / 128), 256, GEMM_SMEM>>>(
        bqkv, nullptr, 0);

    // 2b) V -> V^T bf16 hi/lo
    vt_split<<<dim3(DD / 32, TT / 32, BB * HH), dim3(32, 8)>>>();

    // 3) Attention (pass1 HMMA QK + fp32 softmax, pass2 HMMA AV)
    attn_kernel<<<dim3(TT / 256, HH, BB), 256, ATTN_SMEM>>>();

    // 4) Output projection
    hmma_gemm<<<dim3(CC / 128, BB * TT / 128), 256, GEMM_SMEM>>>(
        bout, out, 1);
}

// round 11
// speedup vs baseline: 2.2374x; 1.1598x over previous
#include <cuda_runtime.h>
#include <cuda_bf16.h>
#include <stdint.h>

#define BB 2
#define TT 2048
#define CC 1024
#define HH 16
#define DD 64

// ---------------------------------------------------------------------------
// Scratch (allocation-free rule: __device__ globals). Device-code refs only.
// ---------------------------------------------------------------------------
__device__ float g_v[BB * HH * TT * DD];
__device__ float g_e[(size_t)BB * HH * TT * TT];
__device__ float g_mh[(size_t)BB * HH * TT * 32];
__device__ uint32_t g_mask[(size_t)BB * HH * TT * (TT / 32)];
// q, k in 3-way bf16 decomposition (h + m + l ~ fp32): [bh][t][d]
__device__ __nv_bfloat16 g_qh[BB * HH * TT * DD], g_qm[BB * HH * TT * DD],
                         g_ql[BB * HH * TT * DD];
__device__ __nv_bfloat16 g_kh[BB * HH * TT * DD], g_km[BB * HH * TT * DD],
                         g_kl[BB * HH * TT * DD];
// split-bf16 GEMM operands
__device__ __nv_bfloat16 g_xh[BB * TT * CC], g_xl[BB * TT * CC];
__device__ __nv_bfloat16 g_wqh[3 * CC * CC], g_wql[3 * CC * CC];
__device__ __nv_bfloat16 g_woh[CC * CC], g_wol[CC * CC];
__device__ __nv_bfloat16 g_aoh[BB * TT * CC], g_aol[BB * TT * CC];
// V transposed per (b,h): [bh][d][t], bf16 hi/lo
__device__ __nv_bfloat16 g_vth[(size_t)BB * HH * DD * TT];
__device__ __nv_bfloat16 g_vtl[(size_t)BB * HH * DD * TT];

// ---------------------------------------------------------------------------
// sm_80-level PTX helpers
// ---------------------------------------------------------------------------
__device__ __forceinline__ uint32_t smem_u32(const void* p) {
    uint32_t a;
    asm("{ .reg .u64 t; cvta.to.shared.u64 t, %1; cvt.u32.u64 %0, t; }"
        : "=r"(a) : "l"(p));
    return a;
}
__device__ __forceinline__ void cp16(uint32_t dst, const void* src) {
    asm volatile("cp.async.cg.shared.global [%0], [%1], 16;"
                 :: "r"(dst), "l"(src) : "memory");
}
#define CP_COMMIT() asm volatile("cp.async.commit_group;" ::: "memory")
#define CP_WAIT(n)  asm volatile("cp.async.wait_group %0;" :: "n"(n) : "memory")

__device__ __forceinline__ void mma16816(float* c, const uint32_t* a,
                                         const uint32_t* b) {
    asm volatile(
        "mma.sync.aligned.m16n8k16.row.col.f32.bf16.bf16.f32 "
        "{%0,%1,%2,%3},{%4,%5,%6,%7},{%8,%9},{%0,%1,%2,%3};"
        : "+f"(c[0]), "+f"(c[1]), "+f"(c[2]), "+f"(c[3])
        : "r"(a[0]), "r"(a[1]), "r"(a[2]), "r"(a[3]), "r"(b[0]), "r"(b[1]));
}
__device__ __forceinline__ uint32_t pk(__nv_bfloat16 a, __nv_bfloat16 b) {
    return (uint32_t)__bfloat16_as_ushort(a) |
           ((uint32_t)__bfloat16_as_ushort(b) << 16);
}
__device__ __forceinline__ void split3(float v, __nv_bfloat16& h,
                                       __nv_bfloat16& m, __nv_bfloat16& l) {
    h = __float2bfloat16(v);
    float r = v - __bfloat162float(h);
    m = __float2bfloat16(r);
    l = __float2bfloat16(r - __bfloat162float(m));
}

// ---------------------------------------------------------------------------
// Threefry-2x32, key = (0, 42)
// ---------------------------------------------------------------------------
__device__ __forceinline__ uint2 threefry_0_42(uint32_t x0, uint32_t x1) {
    const uint32_t ks0 = 0u, ks1 = 42u;
    const uint32_t ks2 = 0x1BD11BDAu ^ ks0 ^ ks1;
    x0 += ks0; x1 += ks1;
#define TF_RND(rot) { x0 += x1; x1 = __funnelshift_l(x1, x1, (rot)); x1 ^= x0; }
    TF_RND(13) TF_RND(15) TF_RND(26) TF_RND(6)
    x0 += ks1; x1 += ks2 + 1u;
    TF_RND(17) TF_RND(29) TF_RND(16) TF_RND(24)
    x0 += ks2; x1 += ks0 + 2u;
    TF_RND(13) TF_RND(15) TF_RND(26) TF_RND(6)
    x0 += ks0; x1 += ks1 + 3u;
    TF_RND(17) TF_RND(29) TF_RND(16) TF_RND(24)
    x0 += ks1; x1 += ks2 + 4u;
    TF_RND(13) TF_RND(15) TF_RND(26) TF_RND(6)
    x0 += ks2; x1 += ks0 + 5u;
#undef TF_RND
    return make_uint2(x0, x1);
}
__device__ __forceinline__ bool regrow_test(uint32_t idx) {
    uint2 rb = threefry_0_42(0u, idx);
    return ((rb.x ^ rb.y) >> 9) <= 419430u;
}

// Two independent threefry chains per thread (ILP 2).
__global__ void __launch_bounds__(256)
mask_kernel() {
    const int t  = blockIdx.y;
    const int bh = blockIdx.z;
    const int wid = threadIdx.x >> 5, lane = threadIdx.x & 31;
    const int w0 = (blockIdx.x * 8 + wid) * 2;
    if (w0 * 32 > t) return;
    const uint32_t base = ((uint32_t)(bh * TT + t)) * (uint32_t)TT;
    bool r0 = regrow_test(base + (uint32_t)(w0 * 32 + lane));
    bool r1 = regrow_test(base + (uint32_t)(w0 * 32 + 32 + lane));
    uint32_t b0 = __ballot_sync(0xffffffffu, r0);
    uint32_t b1 = __ballot_sync(0xffffffffu, r1);
    if (lane == 0) {
        size_t o = ((size_t)(bh * TT + t)) * (TT / 32) + w0;
        g_mask[o] = b0;
        if ((w0 + 1) * 32 <= t) g_mask[o + 1] = b1;
    }
}

// ---------------------------------------------------------------------------
// fp32 -> bf16 hi/lo split: x -> g_xh/g_xl
// ---------------------------------------------------------------------------
__global__ void __launch_bounds__(256)
conv_rows(const float* __restrict__ X, int n4) {
    int i = blockIdx.x * 256 + threadIdx.x;
    if (i >= n4) return;
    float4 v = ((const float4*)X)[i];
    float vv[4] = {v.x, v.y, v.z, v.w};
    __nv_bfloat16 h[4], l[4];
#pragma unroll
    for (int j = 0; j < 4; j++) {
        h[j] = __float2bfloat16(vv[j]);
        l[j] = __float2bfloat16(vv[j] - __bfloat162float(h[j]));
    }
    ((uint32_t*)g_xh)[i * 2]     = pk(h[0], h[1]);
    ((uint32_t*)g_xh)[i * 2 + 1] = pk(h[2], h[3]);
    ((uint32_t*)g_xl)[i * 2]     = pk(l[0], l[1]);
    ((uint32_t*)g_xl)[i * 2 + 1] = pk(l[2], l[3]);
}

// W [K][N] fp32 -> W^T [N][K] bf16 hi/lo.  sel 0: g_wqh/g_wql, 1: g_woh/g_wol
__global__ void __launch_bounds__(256)
conv_tr(const float* __restrict__ W, int K, int N, int sel) {
    __shared__ float sm[32][33];
    __nv_bfloat16* Th = (sel == 0) ? g_wqh : g_woh;
    __nv_bfloat16* Tl = (sel == 0) ? g_wql : g_wol;
    const int n0 = blockIdx.x * 32, k0 = blockIdx.y * 32;
    const int tx = threadIdx.x, ty = threadIdx.y;
#pragma unroll
    for (int i = 0; i < 4; i++)
        sm[ty + i * 8][tx] = W[(size_t)(k0 + ty + i * 8) * N + n0 + tx];
    __syncthreads();
#pragma unroll
    for (int i = 0; i < 4; i++) {
        float v = sm[tx][ty + i * 8];
        __nv_bfloat16 h = __float2bfloat16(v);
        __nv_bfloat16 l = __float2bfloat16(v - __bfloat162float(h));
        size_t o = (size_t)(n0 + ty + i * 8) * K + k0 + tx;
        Th[o] = h; Tl[o] = l;
    }
}

// g_v [bh][t][d] fp32 -> g_vth/g_vtl [bh][d][t] bf16 hi/lo
__global__ void __launch_bounds__(256)
vt_split() {
    __shared__ float sm[32][33];
    const int bh = blockIdx.z;
    const int d0 = blockIdx.x * 32;
    const int t0 = blockIdx.y * 32;
    const int tx = threadIdx.x, ty = threadIdx.y;
    const float* src = g_v + (size_t)bh * TT * DD;
#pragma unroll
    for (int i = 0; i < 4; i++)
        sm[ty + i * 8][tx] = src[(size_t)(t0 + ty + i * 8) * DD + d0 + tx];
    __syncthreads();
#pragma unroll
    for (int i = 0; i < 4; i++) {
        float v = sm[tx][ty + i * 8];
        __nv_bfloat16 h = __float2bfloat16(v);
        __nv_bfloat16 l = __float2bfloat16(v - __bfloat162float(h));
        size_t o = ((size_t)bh * DD + d0 + ty + i * 8) * TT + t0 + tx;
        g_vth[o] = h; g_vtl[o] = l;
    }
}

// ---------------------------------------------------------------------------
// Split-bf16 HMMA GEMM (verified): C = A @ Bt^T + bias.
//   sel 0: A=g_xh/g_xl, Bt=g_wqh/g_wql; scatter q,k as 3-way bf16, v fp32.
//   sel 1: A=g_aoh/g_aol, Bt=g_woh/g_wol; row-major store to Cout.
// ---------------------------------------------------------------------------
#define GOPE   (128 * 40)
#define GSTAGE (4 * GOPE)
#define GEMM_SMEM (2 * GSTAGE * 2)

__global__ void __launch_bounds__(256)
hmma_gemm(const float* __restrict__ bias, float* __restrict__ Cout, int sel) {
    extern __shared__ __nv_bfloat16 gsm[];
    const __nv_bfloat16* Ah = (sel == 0) ? g_xh : g_aoh;
    const __nv_bfloat16* Al = (sel == 0) ? g_xl : g_aol;
    const __nv_bfloat16* Bh = (sel == 0) ? g_wqh : g_woh;
    const __nv_bfloat16* Bl = (sel == 0) ? g_wql : g_wol;
    const int Kdim = CC;
    const int Ncols = (sel == 0) ? 3 * CC : CC;

    const int tid = threadIdx.x;
    const int lane = tid & 31, wid = tid >> 5;
    const int wm = wid & 3, wn = wid >> 2;
    const int n0 = blockIdx.x * 128, m0 = blockIdx.y * 128;
    const int g = lane >> 2, j2 = (lane & 3) * 2;

    float acc[2][8][4];
#pragma unroll
    for (int mi = 0; mi < 2; mi++)
#pragma unroll
        for (int ni = 0; ni < 8; ni++)
#pragma unroll
            for (int r = 0; r < 4; r++) acc[mi][ni][r] = 0.f;

    const int nch = Kdim / 32;

#define ISSUE_LOADS(IT, STAGE) do {                                          \
        const int _k0 = (IT) * 32;                                          \
        __nv_bfloat16* _sb = gsm + (STAGE) * GSTAGE;                         \
        _Pragma("unroll")                                                    \
        for (int _r = 0; _r < 2; _r++) {                                     \
            int _c = _r * 256 + tid;                                         \
            int _row = _c >> 2, _off = (_c & 3) * 8;                         \
            uint32_t _so = smem_u32(_sb + _row * 40 + _off);                 \
            size_t _ga = (size_t)(m0 + _row) * Kdim + _k0 + _off;            \
            size_t _gb = (size_t)(n0 + _row) * Kdim + _k0 + _off;            \
            cp16(_so,                 Ah + _ga);                             \
            cp16(_so + 2 * GOPE,      Al + _ga);                             \
            cp16(_so + 4 * GOPE,      Bh + _gb);                             \
            cp16(_so + 6 * GOPE,      Bl + _gb);                             \
        }                                                                    \
    } while (0)

    ISSUE_LOADS(0, 0);
    CP_COMMIT();

    for (int it = 0; it < nch; it++) {
        if (it + 1 < nch) {
            ISSUE_LOADS(it + 1, (it + 1) & 1);
            CP_COMMIT();
            CP_WAIT(1);
        } else {
            CP_WAIT(0);
        }
        __syncthreads();

        const __nv_bfloat16* sAh = gsm + (it & 1) * GSTAGE;
        const __nv_bfloat16* sAl = sAh + GOPE;
        const __nv_bfloat16* sBh = sAh + 2 * GOPE;
        const __nv_bfloat16* sBl = sAh + 3 * GOPE;

#pragma unroll
        for (int ks = 0; ks < 2; ks++) {
            const int k0 = ks * 16;
            uint32_t ah[2][4], al[2][4], bh[8][2], bl[8][2];
#pragma unroll
            for (int mi = 0; mi < 2; mi++) {
                int row = wm * 32 + mi * 16;
                ah[mi][0] = *(const uint32_t*)&sAh[(row + g) * 40 + k0 + j2];
                ah[mi][1] = *(const uint32_t*)&sAh[(row + 8 + g) * 40 + k0 + j2];
                ah[mi][2] = *(const uint32_t*)&sAh[(row + g) * 40 + k0 + j2 + 8];
                ah[mi][3] = *(const uint32_t*)&sAh[(row + 8 + g) * 40 + k0 + j2 + 8];
                al[mi][0] = *(const uint32_t*)&sAl[(row + g) * 40 + k0 + j2];
                al[mi][1] = *(const uint32_t*)&sAl[(row + 8 + g) * 40 + k0 + j2];
                al[mi][2] = *(const uint32_t*)&sAl[(row + g) * 40 + k0 + j2 + 8];
                al[mi][3] = *(const uint32_t*)&sAl[(row + 8 + g) * 40 + k0 + j2 + 8];
            }
#pragma unroll
            for (int ni = 0; ni < 8; ni++) {
                int n = wn * 64 + ni * 8 + g;
                bh[ni][0] = *(const uint32_t*)&sBh[n * 40 + k0 + j2];
                bh[ni][1] = *(const uint32_t*)&sBh[n * 40 + k0 + j2 + 8];
                bl[ni][0] = *(const uint32_t*)&sBl[n * 40 + k0 + j2];
                bl[ni][1] = *(const uint32_t*)&sBl[n * 40 + k0 + j2 + 8];
            }
#pragma unroll
            for (int mi = 0; mi < 2; mi++)
#pragma unroll
                for (int ni = 0; ni < 8; ni++) {
                    mma16816(acc[mi][ni], ah[mi], bh[ni]);
                    mma16816(acc[mi][ni], ah[mi], bl[ni]);
                    mma16816(acc[mi][ni], al[mi], bh[ni]);
                }
        }
        __syncthreads();
    }

#pragma unroll
    for (int mi = 0; mi < 2; mi++) {
#pragma unroll
        for (int ni = 0; ni < 8; ni++) {
            int m_r = m0 + wm * 32 + mi * 16 + g;
            int n_c = n0 + wn * 64 + ni * 8 + j2;
            float b0 = bias[n_c], b1 = bias[n_c + 1];
            float v00 = acc[mi][ni][0] + b0, v01 = acc[mi][ni][1] + b1;
            float v10 = acc[mi][ni][2] + b0, v11 = acc[mi][ni][3] + b1;
            if (sel == 1) {
                *(float2*)&Cout[(size_t)m_r * Ncols + n_c] = make_float2(v00, v01);
                *(float2*)&Cout[(size_t)(m_r + 8) * Ncols + n_c] = make_float2(v10, v11);
            } else {
                int part = n_c >> 10, rem = n_c & 1023;
                int hh = rem >> 6, dd = rem & 63;
                int b = m_r >> 11, t = m_r & 2047;
                int b2 = (m_r + 8) >> 11, t2 = (m_r + 8) & 2047;
                size_t o1 = (((size_t)b * HH + hh) * TT + t) * DD + dd;
                size_t o2 = (((size_t)b2 * HH + hh) * TT + t2) * DD + dd;
                if (part == 2) {
                    *(float2*)&g_v[o1] = make_float2(v00, v01);
                    *(float2*)&g_v[o2] = make_float2(v10, v11);
                } else {
                    __nv_bfloat16* AH = (part == 0) ? g_qh : g_kh;
                    __nv_bfloat16* AM = (part == 0) ? g_qm : g_km;
                    __nv_bfloat16* AL = (part == 0) ? g_ql : g_kl;
                    __nv_bfloat16 h0, mm0, l0, h1, mm1, l1;
                    split3(v00, h0, mm0, l0);
                    split3(v01, h1, mm1, l1);
                    ((uint32_t*)AH)[o1 >> 1] = pk(h0, h1);
                    ((uint32_t*)AM)[o1 >> 1] = pk(mm0, mm1);
                    ((uint32_t*)AL)[o1 >> 1] = pk(l0, l1);
                    split3(v10, h0, mm0, l0);
                    split3(v11, h1, mm1, l1);
                    ((uint32_t*)AH)[o2 >> 1] = pk(h0, h1);
                    ((uint32_t*)AM)[o2 >> 1] = pk(mm0, mm1);
                    ((uint32_t*)AL)[o2 >> 1] = pk(l0, l1);
                }
            }
        }
    }
#undef ISSUE_LOADS
}

// ---------------------------------------------------------------------------
// Attention, occupancy-2 version.
// Pass 1: 6-term QK HMMA; softmax done directly on MMA fragments (quad
// shuffles), e cached to gmem, running max to g_mh. Pass 2: sparsify + AV
// HMMA (R9/R10-verified fragment maps), vt via cp.async.
// smem 110592 B, 2 blocks/SM, grid 256 = one wave.
//   pass1: q3 [0,55296) | stage0 [55296,82944) | stage1 [82944,110592)
//   pass2: mh [0,16384) | a_smh [16384,34816) | a_sml [34816,53248) |
//          mfin/lfin [53248,54272) | vt stages alias k stages
// ---------------------------------------------------------------------------
#define ATTN_SMEM 110592

__global__ void __launch_bounds__(256, 2)
attn_kernel() {
    extern __shared__ char asmem[];
    __nv_bfloat16* q_sm = (__nv_bfloat16*)asmem;
    __nv_bfloat16* stg0 = (__nv_bfloat16*)(asmem + 55296);
    __nv_bfloat16* stg1 = (__nv_bfloat16*)(asmem + 82944);
    float (*mh_s)[32] = (float(*)[32])asmem;
    __nv_bfloat16* a_smh = (__nv_bfloat16*)(asmem + 16384);
    __nv_bfloat16* a_sml = (__nv_bfloat16*)(asmem + 34816);
    float* mfin = (float*)(asmem + 53248);
    float* lfin = (float*)(asmem + 53760);

    const int NQB = TT / 128;
    const int bh = blockIdx.z * HH + blockIdx.y;
    const int tid = threadIdx.x;
    const int ty = tid >> 4;
    const int tx = tid & 15;
    const int lane = tid & 31, wid = tid >> 5;
    const int wm = wid & 3, wn = wid >> 2;
    const int g = lane >> 2, qd = lane & 3, j2 = qd * 2;

    const uint32_t* qh32 = (const uint32_t*)q_sm;
    const uint32_t* qm32 = qh32 + 4608;
    const uint32_t* ql32 = qh32 + 9216;

    for (int half = 0; half < 2; half++) {
        const int qb = half == 0 ? (NQB - 1 - (int)blockIdx.x) : (int)blockIdx.x;
        const int t0 = qb * 128;
        const int ntiles = 2 * qb + 2;

        // ---- stage q3 via cp.async ----
#pragma unroll
        for (int rep = 0; rep < 12; rep++) {
            int c = rep * 256 + tid;
            int arr = c >> 10, cc = c & 1023, row = cc >> 3, j = cc & 7;
            const __nv_bfloat16* src =
                (arr == 0 ? g_qh : arr == 1 ? g_qm : g_ql) +
                ((size_t)bh * TT + t0 + row) * DD + j * 8;
            cp16(smem_u32(q_sm + arr * 9216 + row * 72 + j * 8), src);
        }
        CP_COMMIT();
        // ---- stage k3 tile 0 ----
#pragma unroll
        for (int rep = 0; rep < 6; rep++) {
            int c = rep * 256 + tid;
            int arr = c >> 9, cc = c & 511, row = cc >> 3, j = cc & 7;
            const __nv_bfloat16* src =
                (arr == 0 ? g_kh : arr == 1 ? g_km : g_kl) +
                ((size_t)bh * TT + row) * DD + j * 8;
            cp16(smem_u32(stg0 + arr * 4608 + row * 72 + j * 8), src);
        }
        CP_COMMIT();
        CP_WAIT(1);               // q done (k0 may still be in flight)
        __syncthreads();

        // ---- Q fragments in registers ----
        uint32_t qfh[4][4], qfm[4][4], qfl[4][4];
#pragma unroll
        for (int ks = 0; ks < 4; ks++) {
            int b0 = (16 * wid + g) * 36 + ks * 8 + qd;
            int b1 = b0 + 8 * 36;
            qfh[ks][0] = qh32[b0]; qfh[ks][1] = qh32[b1];
            qfh[ks][2] = qh32[b0 + 4]; qfh[ks][3] = qh32[b1 + 4];
            qfm[ks][0] = qm32[b0]; qfm[ks][1] = qm32[b1];
            qfm[ks][2] = qm32[b0 + 4]; qfm[ks][3] = qm32[b1 + 4];
            qfl[ks][0] = ql32[b0]; qfl[ks][1] = ql32[b1];
            qfl[ks][2] = ql32[b0 + 4]; qfl[ks][3] = ql32[b1 + 4];
        }

        const int r0 = 16 * wid + g, r1 = r0 + 8;
        const int tg0 = t0 + r0, tg1 = t0 + r1;
        float m0 = -1e30f, m1 = -1e30f, l0 = 0.f, l1 = 0.f;
        float* erow0 = g_e + ((size_t)(bh * TT + tg0)) * TT;
        float* erow1 = g_e + ((size_t)(bh * TT + tg1)) * TT;

        // ---------------- Pass 1 ----------------
        for (int it = 0; it < ntiles; it++) {
            const int s0 = it * 64;
            CP_WAIT(0);
            __syncthreads();
            if (it + 1 < ntiles) {
                __nv_bfloat16* stn = ((it + 1) & 1) ? stg1 : stg0;
#pragma unroll
                for (int rep = 0; rep < 6; rep++) {
                    int c = rep * 256 + tid;
                    int arr = c >> 9, cc = c & 511, row = cc >> 3, j = cc & 7;
                    const __nv_bfloat16* src =
                        (arr == 0 ? g_kh : arr == 1 ? g_km : g_kl) +
                        ((size_t)bh * TT + s0 + 64 + row) * DD + j * 8;
                    cp16(smem_u32(stn + arr * 4608 + row * 72 + j * 8), src);
                }
                CP_COMMIT();
            }

            const uint32_t* kh32s =
                (const uint32_t*)((it & 1) ? stg1 : stg0);
            const uint32_t* km32s = kh32s + 2304;
            const uint32_t* kl32s = kh32s + 4608;

            float acc[8][4];
#pragma unroll
            for (int ni = 0; ni < 8; ni++)
#pragma unroll
                for (int r = 0; r < 4; r++) acc[ni][r] = 0.f;

#pragma unroll
            for (int ks = 0; ks < 4; ks++) {
#pragma unroll
                for (int ni = 0; ni < 8; ni++) {
                    int bb = (ni * 8 + g) * 36 + ks * 8 + qd;
                    uint32_t b_h[2] = {kh32s[bb], kh32s[bb + 4]};
                    uint32_t b_m[2] = {km32s[bb], km32s[bb + 4]};
                    uint32_t b_l[2] = {kl32s[bb], kl32s[bb + 4]};
                    mma16816(acc[ni], qfh[ks], b_h);
                    mma16816(acc[ni], qfm[ks], b_h);
                    mma16816(acc[ni], qfl[ks], b_h);
                    mma16816(acc[ni], qfh[ks], b_m);
                    mma16816(acc[ni], qfm[ks], b_m);
                    mma16816(acc[ni], qfh[ks], b_l);
                }
            }

            // ---- fragment softmax (quad-shuffle reductions) ----
            float tm0 = -1e30f, tm1 = -1e30f;
#pragma unroll
            for (int ni = 0; ni < 8; ni++) {
                int s = s0 + ni * 8 + j2;
                acc[ni][0] = (s     <= tg0) ? acc[ni][0] * 0.125f : -1e30f;
                acc[ni][1] = (s + 1 <= tg0) ? acc[ni][1] * 0.125f : -1e30f;
                acc[ni][2] = (s     <= tg1) ? acc[ni][2] * 0.125f : -1e30f;
                acc[ni][3] = (s + 1 <= tg1) ? acc[ni][3] * 0.125f : -1e30f;
                tm0 = fmaxf(tm0, fmaxf(acc[ni][0], acc[ni][1]));
                tm1 = fmaxf(tm1, fmaxf(acc[ni][2], acc[ni][3]));
            }
            tm0 = fmaxf(tm0, __shfl_xor_sync(0xffffffffu, tm0, 1));
            tm0 = fmaxf(tm0, __shfl_xor_sync(0xffffffffu, tm0, 2));
            tm1 = fmaxf(tm1, __shfl_xor_sync(0xffffffffu, tm1, 1));
            tm1 = fmaxf(tm1, __shfl_xor_sync(0xffffffffu, tm1, 2));
            float mn0 = fmaxf(m0, tm0), mn1 = fmaxf(m1, tm1);
            float ls0 = 0.f, ls1 = 0.f;
#pragma unroll
            for (int ni = 0; ni < 8; ni++) {
                acc[ni][0] = __expf(acc[ni][0] - mn0);
                acc[ni][1] = __expf(acc[ni][1] - mn0);
                acc[ni][2] = __expf(acc[ni][2] - mn1);
                acc[ni][3] = __expf(acc[ni][3] - mn1);
                ls0 += acc[ni][0] + acc[ni][1];
                ls1 += acc[ni][2] + acc[ni][3];
            }
            ls0 += __shfl_xor_sync(0xffffffffu, ls0, 1);
            ls0 += __shfl_xor_sync(0xffffffffu, ls0, 2);
            ls1 += __shfl_xor_sync(0xffffffffu, ls1, 1);
            ls1 += __shfl_xor_sync(0xffffffffu, ls1, 2);
            l0 = l0 * __expf(m0 - mn0) + ls0; m0 = mn0;
            l1 = l1 * __expf(m1 - mn1) + ls1; m1 = mn1;

#pragma unroll
            for (int ni = 0; ni < 8; ni++) {
                *(float2*)&erow0[s0 + ni * 8 + j2] =
                    make_float2(acc[ni][0], acc[ni][1]);
                *(float2*)&erow1[s0 + ni * 8 + j2] =
                    make_float2(acc[ni][2], acc[ni][3]);
            }
            if (qd == 0) {
                g_mh[((size_t)(bh * TT + tg0)) * 32 + it] = mn0;
                g_mh[((size_t)(bh * TT + tg1)) * 32 + it] = mn1;
            }
        }

        __syncthreads();
        if (qd == 0) {
            mfin[r0] = m0; lfin[r0] = 1.0f / l0;
            mfin[r1] = m1; lfin[r1] = 1.0f / l1;
        }
        // issue vt tile 0 while factors compute
#pragma unroll
        for (int rep = 0; rep < 4; rep++) {
            int c = rep * 256 + tid;
            int arr = c >> 9, cc = c & 511, d = cc >> 3, j = cc & 7;
            const __nv_bfloat16* src =
                (arr ? g_vtl : g_vth) + ((size_t)bh * DD + d) * TT + j * 8;
            cp16(smem_u32(stg0 + arr * 4608 + d * 72 + j * 8), src);
        }
        CP_COMMIT();
        __syncthreads();

        // factors c_it = exp(mh - m_fin) / l into mh_s
#pragma unroll
        for (int i = 0; i < 8; i++) {
            int row = ty * 8 + i;
            float mf = mfin[row], il = lfin[row];
            for (int it2 = tx; it2 < ntiles; it2 += 16)
                mh_s[row][it2] =
                    __expf(g_mh[((size_t)(bh * TT + t0 + row)) * 32 + it2] - mf) * il;
        }

        // ---------------- Pass 2 ----------------
        float acc2[2][4][4];
#pragma unroll
        for (int mi = 0; mi < 2; mi++)
#pragma unroll
            for (int ni = 0; ni < 4; ni++)
#pragma unroll
                for (int r = 0; r < 4; r++) acc2[mi][ni][r] = 0.f;

        for (int it = 0; it < ntiles; it++) {
            const int s0 = it * 64;
            CP_WAIT(0);
            __syncthreads();
            if (it + 1 < ntiles) {
                __nv_bfloat16* stn = ((it + 1) & 1) ? stg1 : stg0;
#pragma unroll
                for (int rep = 0; rep < 4; rep++) {
                    int c = rep * 256 + tid;
                    int arr = c >> 9, cc = c & 511, d = cc >> 3, j = cc & 7;
                    const __nv_bfloat16* src = (arr ? g_vtl : g_vth) +
                        ((size_t)bh * DD + d) * TT + s0 + 64 + j * 8;
                    cp16(smem_u32(stn + arr * 4608 + d * 72 + j * 8), src);
                }
                CP_COMMIT();
            }

            // sparsify + split a into bf16 hi/lo
#pragma unroll
            for (int i = 0; i < 8; i++) {
                const int row = ty * 8 + i;
                const int t = t0 + row;
                const float fac = mh_s[row][it];
                const float* erow = g_e + ((size_t)(bh * TT + t)) * TT;
                float4 ev = *(const float4*)&erow[s0 + tx * 4];
                uint32_t word = g_mask[((size_t)(bh * TT + t)) * (TT / 32) +
                                       (s0 >> 5) + (tx >> 3)];
                int bp = (tx & 7) * 4;
                float a0 = ev.x * fac, a1 = ev.y * fac,
                      a2 = ev.z * fac, a3 = ev.w * fac;
                a0 = (a0 > 0.01f || ((word >> (bp + 0)) & 1u)) ? a0 : 0.f;
                a1 = (a1 > 0.01f || ((word >> (bp + 1)) & 1u)) ? a1 : 0.f;
                a2 = (a2 > 0.01f || ((word >> (bp + 2)) & 1u)) ? a2 : 0.f;
                a3 = (a3 > 0.01f || ((word >> (bp + 3)) & 1u)) ? a3 : 0.f;
                __nv_bfloat16 h0 = __float2bfloat16(a0), h1 = __float2bfloat16(a1);
                __nv_bfloat16 h2 = __float2bfloat16(a2), h3 = __float2bfloat16(a3);
                __nv_bfloat16 lo0 = __float2bfloat16(a0 - __bfloat162float(h0));
                __nv_bfloat16 lo1 = __float2bfloat16(a1 - __bfloat162float(h1));
                __nv_bfloat16 lo2 = __float2bfloat16(a2 - __bfloat162float(h2));
                __nv_bfloat16 lo3 = __float2bfloat16(a3 - __bfloat162float(h3));
                uint32_t idx = row * 36 + tx * 2;
                ((uint32_t*)a_smh)[idx]     = pk(h0, h1);
                ((uint32_t*)a_smh)[idx + 1] = pk(h2, h3);
                ((uint32_t*)a_sml)[idx]     = pk(lo0, lo1);
                ((uint32_t*)a_sml)[idx + 1] = pk(lo2, lo3);
            }
            __syncthreads();

            const uint32_t* ah32 = (const uint32_t*)a_smh;
            const uint32_t* al32 = (const uint32_t*)a_sml;
            const uint32_t* vh32 =
                (const uint32_t*)((it & 1) ? stg1 : stg0);
            const uint32_t* vl32 = vh32 + 2304;
#pragma unroll
            for (int ks = 0; ks < 4; ks++) {
                uint32_t ah[2][4], al[2][4], bh[4][2], bl[4][2];
#pragma unroll
                for (int mi = 0; mi < 2; mi++) {
                    int base = (wm * 32 + mi * 16 + g) * 36 + ks * 8 + qd;
                    ah[mi][0] = ah32[base];
                    ah[mi][1] = ah32[base + 8 * 36];
                    ah[mi][2] = ah32[base + 4];
                    ah[mi][3] = ah32[base + 8 * 36 + 4];
                    al[mi][0] = al32[base];
                    al[mi][1] = al32[base + 8 * 36];
                    al[mi][2] = al32[base + 4];
                    al[mi][3] = al32[base + 8 * 36 + 4];
                }
#pragma unroll
                for (int ni = 0; ni < 4; ni++) {
                    int base = (wn * 32 + ni * 8 + g) * 36 + ks * 8 + qd;
                    bh[ni][0] = vh32[base];
                    bh[ni][1] = vh32[base + 4];
                    bl[ni][0] = vl32[base];
                    bl[ni][1] = vl32[base + 4];
                }
#pragma unroll
                for (int mi = 0; mi < 2; mi++)
#pragma unroll
                    for (int ni = 0; ni < 4; ni++) {
                        mma16816(acc2[mi][ni], ah[mi], bh[ni]);
                        mma16816(acc2[mi][ni], ah[mi], bl[ni]);
                        mma16816(acc2[mi][ni], al[mi], bh[ni]);
                    }
            }
        }

        // epilogue: split output, write g_aoh/g_aol directly
        const int b = blockIdx.z, h = blockIdx.y;
#pragma unroll
        for (int mi = 0; mi < 2; mi++) {
#pragma unroll
            for (int ni = 0; ni < 4; ni++) {
                int mrow = wm * 32 + mi * 16 + g;
                int n = wn * 32 + ni * 8 + j2;
#pragma unroll
                for (int rr = 0; rr < 2; rr++) {
                    int t = t0 + mrow + rr * 8;
                    float v0 = acc2[mi][ni][rr * 2 + 0];
                    float v1 = acc2[mi][ni][rr * 2 + 1];
                    __nv_bfloat16 h0 = __float2bfloat16(v0);
                    __nv_bfloat16 h1 = __float2bfloat16(v1);
                    __nv_bfloat16 lo0 = __float2bfloat16(v0 - __bfloat162float(h0));
                    __nv_bfloat16 lo1 = __float2bfloat16(v1 - __bfloat162float(h1));
                    size_t o = ((size_t)(b * TT + t) * CC + h * 64 + n) >> 1;
                    ((uint32_t*)g_aoh)[o] = pk(h0, h1);
                    ((uint32_t*)g_aol)[o] = pk(lo0, lo1);
                }
            }
        }
        __syncthreads();
    }
}

// ---------------------------------------------------------------------------
extern "C" void kernel_launch(void* const* d_in, const int* in_sizes, int n_in,
                              void* d_out, int out_size) {
    const float* x    = (const float*)d_in[0];
    const float* Wqkv = (const float*)d_in[1];
    const float* bqkv = (const float*)d_in[2];
    const float* Wout = (const float*)d_in[3];
    const float* bout = (const float*)d_in[4];
    float* out = (float*)d_out;

    cudaFuncSetAttribute(attn_kernel,
                         cudaFuncAttributeMaxDynamicSharedMemorySize, ATTN_SMEM);
    cudaFuncSetAttribute(hmma_gemm,
                         cudaFuncAttributeMaxDynamicSharedMemorySize, GEMM_SMEM);

    // 0) Regrow bitmask (input-independent)
    mask_kernel<<<dim3(4, TT, BB * HH), 256>>>();

    // 1) Split-bf16 conversions
    conv_rows<<<(BB * TT * CC / 4 + 255) / 256, 256>>>(x, BB * TT * CC / 4);
    conv_tr<<<dim3(3 * CC / 32, CC / 32), dim3(32, 8)>>>(Wqkv, CC, 3 * CC, 0);
    conv_tr<<<dim3(CC / 32, CC / 32), dim3(32, 8)>>>(Wout, CC, CC, 1);

    // 2) QKV projection -> q,k (3-way bf16), v (fp32)
    hmma_gemm<<<dim3(3 * CC / 128, BB * TT / 128), 256, GEMM_SMEM>>>(
        bqkv, nullptr, 0);

    // 2b) V -> V^T bf16 hi/lo
    vt_split<<<dim3(DD / 32, TT / 32, BB * HH), dim3(32, 8)>>>();

    // 3) Attention (pass1 HMMA QK + fragment softmax, pass2 HMMA AV)
    attn_kernel<<<dim3(TT / 256, HH, BB), 256, ATTN_SMEM>>>();

    // 4) Output projection
    hmma_gemm<<<dim3(CC / 128, BB * TT / 128), 256, GEMM_SMEM>>>(
        bout, out, 1);
}

// round 13
// speedup vs baseline: 2.4248x; 1.0838x over previous
#include <cuda_runtime.h>
#include <cuda_fp16.h>
#include <stdint.h>

#define BB 2
#define TT 2048
#define CC 1024
#define HH 16
#define DD 64

// ---------------------------------------------------------------------------
// Scratch (allocation-free rule: __device__ globals). Device-code refs only.
// ---------------------------------------------------------------------------
__device__ float g_v[BB * HH * TT * DD];
__device__ float g_e[(size_t)BB * HH * TT * TT];   // fp32: precision-critical
__device__ float g_mh[(size_t)BB * HH * TT * 32];
__device__ uint32_t g_mask[(size_t)BB * HH * TT * (TT / 32)];
// q, k in 2-way f16 decomposition (h + l ~ fp32): [bh][t][d]
__device__ __half g_qh[BB * HH * TT * DD], g_ql[BB * HH * TT * DD];
__device__ __half g_kh[BB * HH * TT * DD], g_kl[BB * HH * TT * DD];
// split-f16 GEMM operands
__device__ __half g_xh[BB * TT * CC], g_xl[BB * TT * CC];
__device__ __half g_wqh[3 * CC * CC], g_wql[3 * CC * CC];
__device__ __half g_woh[CC * CC], g_wol[CC * CC];
__device__ __half g_aoh[BB * TT * CC], g_aol[BB * TT * CC];
// V transposed per (b,h): [bh][d][t], f16 hi/lo
__device__ __half g_vth[(size_t)BB * HH * DD * TT];
__device__ __half g_vtl[(size_t)BB * HH * DD * TT];

// ---------------------------------------------------------------------------
// sm_80-level PTX helpers
// ---------------------------------------------------------------------------
__device__ __forceinline__ uint32_t smem_u32(const void* p) {
    uint32_t a;
    asm("{ .reg .u64 t; cvta.to.shared.u64 t, %1; cvt.u32.u64 %0, t; }"
        : "=r"(a) : "l"(p));
    return a;
}
__device__ __forceinline__ void cp16(uint32_t dst, const void* src) {
    asm volatile("cp.async.cg.shared.global [%0], [%1], 16;"
                 :: "r"(dst), "l"(src) : "memory");
}
#define CP_COMMIT() asm volatile("cp.async.commit_group;" ::: "memory")
#define CP_WAIT(n)  asm volatile("cp.async.wait_group %0;" :: "n"(n) : "memory")

// f16 x f16 -> f32 accumulate MMA
__device__ __forceinline__ void mma16816(float* c, const uint32_t* a,
                                         const uint32_t* b) {
    asm volatile(
        "mma.sync.aligned.m16n8k16.row.col.f32.f16.f16.f32 "
        "{%0,%1,%2,%3},{%4,%5,%6,%7},{%8,%9},{%0,%1,%2,%3};"
        : "+f"(c[0]), "+f"(c[1]), "+f"(c[2]), "+f"(c[3])
        : "r"(a[0]), "r"(a[1]), "r"(a[2]), "r"(a[3]), "r"(b[0]), "r"(b[1]));
}
__device__ __forceinline__ uint32_t pk(__half a, __half b) {
    return (uint32_t)__half_as_ushort(a) |
           ((uint32_t)__half_as_ushort(b) << 16);
}
__device__ __forceinline__ void split2(float v, __half& h, __half& l) {
    h = __float2half_rn(v);
    l = __float2half_rn(v - __half2float(h));
}

// ---------------------------------------------------------------------------
// Threefry-2x32, key = (0, 42)
// ---------------------------------------------------------------------------
__device__ __forceinline__ uint2 threefry_0_42(uint32_t x0, uint32_t x1) {
    const uint32_t ks0 = 0u, ks1 = 42u;
    const uint32_t ks2 = 0x1BD11BDAu ^ ks0 ^ ks1;
    x0 += ks0; x1 += ks1;
#define TF_RND(rot) { x0 += x1; x1 = __funnelshift_l(x1, x1, (rot)); x1 ^= x0; }
    TF_RND(13) TF_RND(15) TF_RND(26) TF_RND(6)
    x0 += ks1; x1 += ks2 + 1u;
    TF_RND(17) TF_RND(29) TF_RND(16) TF_RND(24)
    x0 += ks2; x1 += ks0 + 2u;
    TF_RND(13) TF_RND(15) TF_RND(26) TF_RND(6)
    x0 += ks0; x1 += ks1 + 3u;
    TF_RND(17) TF_RND(29) TF_RND(16) TF_RND(24)
    x0 += ks1; x1 += ks2 + 4u;
    TF_RND(13) TF_RND(15) TF_RND(26) TF_RND(6)
    x0 += ks2; x1 += ks0 + 5u;
#undef TF_RND
    return make_uint2(x0, x1);
}
__device__ __forceinline__ bool regrow_test(uint32_t idx) {
    uint2 rb = threefry_0_42(0u, idx);
    return ((rb.x ^ rb.y) >> 9) <= 419430u;
}

// Two independent threefry chains per thread (ILP 2).
__global__ void __launch_bounds__(256)
mask_kernel() {
    const int t  = blockIdx.y;
    const int bh = blockIdx.z;
    const int wid = threadIdx.x >> 5, lane = threadIdx.x & 31;
    const int w0 = (blockIdx.x * 8 + wid) * 2;
    if (w0 * 32 > t) return;
    const uint32_t base = ((uint32_t)(bh * TT + t)) * (uint32_t)TT;
    bool r0 = regrow_test(base + (uint32_t)(w0 * 32 + lane));
    bool r1 = regrow_test(base + (uint32_t)(w0 * 32 + 32 + lane));
    uint32_t b0 = __ballot_sync(0xffffffffu, r0);
    uint32_t b1 = __ballot_sync(0xffffffffu, r1);
    if (lane == 0) {
        size_t o = ((size_t)(bh * TT + t)) * (TT / 32) + w0;
        g_mask[o] = b0;
        if ((w0 + 1) * 32 <= t) g_mask[o + 1] = b1;
    }
}

// ---------------------------------------------------------------------------
// fp32 -> f16 hi/lo split: x -> g_xh/g_xl
// ---------------------------------------------------------------------------
__global__ void __launch_bounds__(256)
conv_rows(const float* __restrict__ X, int n4) {
    int i = blockIdx.x * 256 + threadIdx.x;
    if (i >= n4) return;
    float4 v = ((const float4*)X)[i];
    float vv[4] = {v.x, v.y, v.z, v.w};
    __half h[4], l[4];
#pragma unroll
    for (int j = 0; j < 4; j++) split2(vv[j], h[j], l[j]);
    ((uint32_t*)g_xh)[i * 2]     = pk(h[0], h[1]);
    ((uint32_t*)g_xh)[i * 2 + 1] = pk(h[2], h[3]);
    ((uint32_t*)g_xl)[i * 2]     = pk(l[0], l[1]);
    ((uint32_t*)g_xl)[i * 2 + 1] = pk(l[2], l[3]);
}

// W [K][N] fp32 -> W^T [N][K] f16 hi/lo.  sel 0: g_wqh/g_wql, 1: g_woh/g_wol
__global__ void __launch_bounds__(256)
conv_tr(const float* __restrict__ W, int K, int N, int sel) {
    __shared__ float sm[32][33];
    __half* Th = (sel == 0) ? g_wqh : g_woh;
    __half* Tl = (sel == 0) ? g_wql : g_wol;
    const int n0 = blockIdx.x * 32, k0 = blockIdx.y * 32;
    const int tx = threadIdx.x, ty = threadIdx.y;
#pragma unroll
    for (int i = 0; i < 4; i++)
        sm[ty + i * 8][tx] = W[(size_t)(k0 + ty + i * 8) * N + n0 + tx];
    __syncthreads();
#pragma unroll
    for (int i = 0; i < 4; i++) {
        float v = sm[tx][ty + i * 8];
        __half h, l;
        split2(v, h, l);
        size_t o = (size_t)(n0 + ty + i * 8) * K + k0 + tx;
        Th[o] = h; Tl[o] = l;
    }
}

// g_v [bh][t][d] fp32 -> g_vth/g_vtl [bh][d][t] f16 hi/lo
__global__ void __launch_bounds__(256)
vt_split() {
    __shared__ float sm[32][33];
    const int bh = blockIdx.z;
    const int d0 = blockIdx.x * 32;
    const int t0 = blockIdx.y * 32;
    const int tx = threadIdx.x, ty = threadIdx.y;
    const float* src = g_v + (size_t)bh * TT * DD;
#pragma unroll
    for (int i = 0; i < 4; i++)
        sm[ty + i * 8][tx] = src[(size_t)(t0 + ty + i * 8) * DD + d0 + tx];
    __syncthreads();
#pragma unroll
    for (int i = 0; i < 4; i++) {
        float v = sm[tx][ty + i * 8];
        __half h, l;
        split2(v, h, l);
        size_t o = ((size_t)bh * DD + d0 + ty + i * 8) * TT + t0 + tx;
        g_vth[o] = h; g_vtl[o] = l;
    }
}

// ---------------------------------------------------------------------------
// Split-f16 HMMA GEMM: C = A @ Bt^T + bias.
//   sel 0: A=g_xh/g_xl, Bt=g_wqh/g_wql; scatter q,k as 2-way f16, v fp32.
//   sel 1: A=g_aoh/g_aol, Bt=g_woh/g_wol; row-major store to Cout.
// ---------------------------------------------------------------------------
#define GOPE   (128 * 40)
#define GSTAGE (4 * GOPE)
#define GEMM_SMEM (2 * GSTAGE * 2)

__global__ void __launch_bounds__(256)
hmma_gemm(const float* __restrict__ bias, float* __restrict__ Cout, int sel) {
    extern __shared__ __half gsm[];
    const __half* Ah = (sel == 0) ? g_xh : g_aoh;
    const __half* Al = (sel == 0) ? g_xl : g_aol;
    const __half* Bh = (sel == 0) ? g_wqh : g_woh;
    const __half* Bl = (sel == 0) ? g_wql : g_wol;
    const int Kdim = CC;
    const int Ncols = (sel == 0) ? 3 * CC : CC;

    const int tid = threadIdx.x;
    const int lane = tid & 31, wid = tid >> 5;
    const int wm = wid & 3, wn = wid >> 2;
    const int n0 = blockIdx.x * 128, m0 = blockIdx.y * 128;
    const int g = lane >> 2, j2 = (lane & 3) * 2;

    float acc[2][8][4];
#pragma unroll
    for (int mi = 0; mi < 2; mi++)
#pragma unroll
        for (int ni = 0; ni < 8; ni++)
#pragma unroll
            for (int r = 0; r < 4; r++) acc[mi][ni][r] = 0.f;

    const int nch = Kdim / 32;

#define ISSUE_LOADS(IT, STAGE) do {                                          \
        const int _k0 = (IT) * 32;                                          \
        __half* _sb = gsm + (STAGE) * GSTAGE;                               \
        _Pragma("unroll")                                                    \
        for (int _r = 0; _r < 2; _r++) {                                     \
            int _c = _r * 256 + tid;                                         \
            int _row = _c >> 2, _off = (_c & 3) * 8;                         \
            uint32_t _so = smem_u32(_sb + _row * 40 + _off);                 \
            size_t _ga = (size_t)(m0 + _row) * Kdim + _k0 + _off;            \
            size_t _gb = (size_t)(n0 + _row) * Kdim + _k0 + _off;            \
            cp16(_so,                 Ah + _ga);                             \
            cp16(_so + 2 * GOPE,      Al + _ga);                             \
            cp16(_so + 4 * GOPE,      Bh + _gb);                             \
            cp16(_so + 6 * GOPE,      Bl + _gb);                             \
        }                                                                    \
    } while (0)

    ISSUE_LOADS(0, 0);
    CP_COMMIT();

    for (int it = 0; it < nch; it++) {
        if (it + 1 < nch) {
            ISSUE_LOADS(it + 1, (it + 1) & 1);
            CP_COMMIT();
            CP_WAIT(1);
        } else {
            CP_WAIT(0);
        }
        __syncthreads();

        const __half* sAh = gsm + (it & 1) * GSTAGE;
        const __half* sAl = sAh + GOPE;
        const __half* sBh = sAh + 2 * GOPE;
        const __half* sBl = sAh + 3 * GOPE;

#pragma unroll
        for (int ks = 0; ks < 2; ks++) {
            const int k0 = ks * 16;
            uint32_t ah[2][4], al[2][4], bh[8][2], bl[8][2];
#pragma unroll
            for (int mi = 0; mi < 2; mi++) {
                int row = wm * 32 + mi * 16;
                ah[mi][0] = *(const uint32_t*)&sAh[(row + g) * 40 + k0 + j2];
                ah[mi][1] = *(const uint32_t*)&sAh[(row + 8 + g) * 40 + k0 + j2];
                ah[mi][2] = *(const uint32_t*)&sAh[(row + g) * 40 + k0 + j2 + 8];
                ah[mi][3] = *(const uint32_t*)&sAh[(row + 8 + g) * 40 + k0 + j2 + 8];
                al[mi][0] = *(const uint32_t*)&sAl[(row + g) * 40 + k0 + j2];
                al[mi][1] = *(const uint32_t*)&sAl[(row + 8 + g) * 40 + k0 + j2];
                al[mi][2] = *(const uint32_t*)&sAl[(row + g) * 40 + k0 + j2 + 8];
                al[mi][3] = *(const uint32_t*)&sAl[(row + 8 + g) * 40 + k0 + j2 + 8];
            }
#pragma unroll
            for (int ni = 0; ni < 8; ni++) {
                int n = wn * 64 + ni * 8 + g;
                bh[ni][0] = *(const uint32_t*)&sBh[n * 40 + k0 + j2];
                bh[ni][1] = *(const uint32_t*)&sBh[n * 40 + k0 + j2 + 8];
                bl[ni][0] = *(const uint32_t*)&sBl[n * 40 + k0 + j2];
                bl[ni][1] = *(const uint32_t*)&sBl[n * 40 + k0 + j2 + 8];
            }
#pragma unroll
            for (int mi = 0; mi < 2; mi++)
#pragma unroll
                for (int ni = 0; ni < 8; ni++) {
                    mma16816(acc[mi][ni], ah[mi], bh[ni]);
                    mma16816(acc[mi][ni], ah[mi], bl[ni]);
                    mma16816(acc[mi][ni], al[mi], bh[ni]);
                }
        }
        __syncthreads();
    }

#pragma unroll
    for (int mi = 0; mi < 2; mi++) {
#pragma unroll
        for (int ni = 0; ni < 8; ni++) {
            int m_r = m0 + wm * 32 + mi * 16 + g;
            int n_c = n0 + wn * 64 + ni * 8 + j2;
            float b0 = bias[n_c], b1 = bias[n_c + 1];
            float v00 = acc[mi][ni][0] + b0, v01 = acc[mi][ni][1] + b1;
            float v10 = acc[mi][ni][2] + b0, v11 = acc[mi][ni][3] + b1;
            if (sel == 1) {
                *(float2*)&Cout[(size_t)m_r * Ncols + n_c] = make_float2(v00, v01);
                *(float2*)&Cout[(size_t)(m_r + 8) * Ncols + n_c] = make_float2(v10, v11);
            } else {
                int part = n_c >> 10, rem = n_c & 1023;
                int hh = rem >> 6, dd = rem & 63;
                int b = m_r >> 11, t = m_r & 2047;
                int b2 = (m_r + 8) >> 11, t2 = (m_r + 8) & 2047;
                size_t o1 = (((size_t)b * HH + hh) * TT + t) * DD + dd;
                size_t o2 = (((size_t)b2 * HH + hh) * TT + t2) * DD + dd;
                if (part == 2) {
                    *(float2*)&g_v[o1] = make_float2(v00, v01);
                    *(float2*)&g_v[o2] = make_float2(v10, v11);
                } else {
                    __half* AH = (part == 0) ? g_qh : g_kh;
                    __half* AL = (part == 0) ? g_ql : g_kl;
                    __half h0, l0, h1, l1;
                    split2(v00, h0, l0);
                    split2(v01, h1, l1);
                    ((uint32_t*)AH)[o1 >> 1] = pk(h0, h1);
                    ((uint32_t*)AL)[o1 >> 1] = pk(l0, l1);
                    split2(v10, h0, l0);
                    split2(v11, h1, l1);
                    ((uint32_t*)AH)[o2 >> 1] = pk(h0, h1);
                    ((uint32_t*)AL)[o2 >> 1] = pk(l0, l1);
                }
            }
        }
    }
#undef ISSUE_LOADS
}

// ---------------------------------------------------------------------------
// Attention, f16 2-way splits (3-term MMAs), occupancy 2, e cached fp32.
// Pass 1: QK HMMA + fragment softmax (quad shuffles), e -> g_e (fp32).
// Pass 2: sparsify + AV HMMA.
// smem layout (91136 B, 2 blocks/SM):
//   stgA [0,18432) | stgB [18432,36864)   (k / vt tiles, both passes)
//   pass1: q2 [36864,73728)
//   pass2: mh [36864,53248) | a_h [53248,71680) | a_l [71680,90112) |
//          mfin [90112,90624) | lfin [90624,91136)
// ---------------------------------------------------------------------------
#define ATTN_SMEM 91136

__global__ void __launch_bounds__(256, 2)
attn_kernel() {
    extern __shared__ char asmem[];
    __half* stgA = (__half*)asmem;
    __half* stgB = (__half*)(asmem + 18432);
    __half* q_sm = (__half*)(asmem + 36864);
    float (*mh_s)[32] = (float(*)[32])(asmem + 36864);
    __half* a_smh = (__half*)(asmem + 53248);
    __half* a_sml = (__half*)(asmem + 71680);
    float* mfin = (float*)(asmem + 90112);
    float* lfin = (float*)(asmem + 90624);

    const int NQB = TT / 128;
    const int bh = blockIdx.z * HH + blockIdx.y;
    const int tid = threadIdx.x;
    const int ty = tid >> 4;
    const int tx = tid & 15;
    const int lane = tid & 31, wid = tid >> 5;
    const int wm = wid & 3, wn = wid >> 2;
    const int g = lane >> 2, qd = lane & 3, j2 = qd * 2;

    const uint32_t* qh32 = (const uint32_t*)q_sm;
    const uint32_t* ql32 = qh32 + 4608;

    for (int half = 0; half < 2; half++) {
        const int qb = half == 0 ? (NQB - 1 - (int)blockIdx.x) : (int)blockIdx.x;
        const int t0 = qb * 128;
        const int ntiles = 2 * qb + 2;

        // ---- stage q2 via cp.async (2048 chunks, 8/thread) ----
#pragma unroll
        for (int rep = 0; rep < 8; rep++) {
            int c = rep * 256 + tid;
            int arr = c >> 10, cc = c & 1023, row = cc >> 3, j = cc & 7;
            const __half* src = (arr == 0 ? g_qh : g_ql) +
                ((size_t)bh * TT + t0 + row) * DD + j * 8;
            cp16(smem_u32(q_sm + arr * 9216 + row * 72 + j * 8), src);
        }
        CP_COMMIT();
        // ---- stage k2 tile 0 (1024 chunks, 4/thread) ----
#pragma unroll
        for (int rep = 0; rep < 4; rep++) {
            int c = rep * 256 + tid;
            int arr = c >> 9, cc = c & 511, row = cc >> 3, j = cc & 7;
            const __half* src = (arr == 0 ? g_kh : g_kl) +
                ((size_t)bh * TT + row) * DD + j * 8;
            cp16(smem_u32(stgA + arr * 4608 + row * 72 + j * 8), src);
        }
        CP_COMMIT();
        CP_WAIT(1);               // q done (k0 may still be in flight)
        __syncthreads();

        // ---- Q fragments in registers ----
        uint32_t qfh[4][4], qfl[4][4];
#pragma unroll
        for (int ks = 0; ks < 4; ks++) {
            int b0 = (16 * wid + g) * 36 + ks * 8 + qd;
            int b1 = b0 + 8 * 36;
            qfh[ks][0] = qh32[b0]; qfh[ks][1] = qh32[b1];
            qfh[ks][2] = qh32[b0 + 4]; qfh[ks][3] = qh32[b1 + 4];
            qfl[ks][0] = ql32[b0]; qfl[ks][1] = ql32[b1];
            qfl[ks][2] = ql32[b0 + 4]; qfl[ks][3] = ql32[b1 + 4];
        }

        const int r0 = 16 * wid + g, r1 = r0 + 8;
        const int tg0 = t0 + r0, tg1 = t0 + r1;
        float m0 = -1e30f, m1 = -1e30f, l0 = 0.f, l1 = 0.f;
        float* erow0 = g_e + ((size_t)(bh * TT + tg0)) * TT;
        float* erow1 = g_e + ((size_t)(bh * TT + tg1)) * TT;

        // ---------------- Pass 1 ----------------
        for (int it = 0; it < ntiles; it++) {
            const int s0 = it * 64;
            CP_WAIT(0);
            __syncthreads();
            if (it + 1 < ntiles) {
                __half* stn = ((it + 1) & 1) ? stgB : stgA;
#pragma unroll
                for (int rep = 0; rep < 4; rep++) {
                    int c = rep * 256 + tid;
                    int arr = c >> 9, cc = c & 511, row = cc >> 3, j = cc & 7;
                    const __half* src = (arr == 0 ? g_kh : g_kl) +
                        ((size_t)bh * TT + s0 + 64 + row) * DD + j * 8;
                    cp16(smem_u32(stn + arr * 4608 + row * 72 + j * 8), src);
                }
                CP_COMMIT();
            }

            const uint32_t* kh32s =
                (const uint32_t*)((it & 1) ? stgB : stgA);
            const uint32_t* kl32s = kh32s + 2304;

            float acc[8][4];
#pragma unroll
            for (int ni = 0; ni < 8; ni++)
#pragma unroll
                for (int r = 0; r < 4; r++) acc[ni][r] = 0.f;

#pragma unroll
            for (int ks = 0; ks < 4; ks++) {
#pragma unroll
                for (int ni = 0; ni < 8; ni++) {
                    int bb = (ni * 8 + g) * 36 + ks * 8 + qd;
                    uint32_t b_h[2] = {kh32s[bb], kh32s[bb + 4]};
                    uint32_t b_l[2] = {kl32s[bb], kl32s[bb + 4]};
                    mma16816(acc[ni], qfh[ks], b_h);
                    mma16816(acc[ni], qfl[ks], b_h);
                    mma16816(acc[ni], qfh[ks], b_l);
                }
            }

            // ---- fragment softmax (quad-shuffle reductions) ----
            float tm0 = -1e30f, tm1 = -1e30f;
#pragma unroll
            for (int ni = 0; ni < 8; ni++) {
                int s = s0 + ni * 8 + j2;
                acc[ni][0] = (s     <= tg0) ? acc[ni][0] * 0.125f : -1e30f;
                acc[ni][1] = (s + 1 <= tg0) ? acc[ni][1] * 0.125f : -1e30f;
                acc[ni][2] = (s     <= tg1) ? acc[ni][2] * 0.125f : -1e30f;
                acc[ni][3] = (s + 1 <= tg1) ? acc[ni][3] * 0.125f : -1e30f;
                tm0 = fmaxf(tm0, fmaxf(acc[ni][0], acc[ni][1]));
                tm1 = fmaxf(tm1, fmaxf(acc[ni][2], acc[ni][3]));
            }
            tm0 = fmaxf(tm0, __shfl_xor_sync(0xffffffffu, tm0, 1));
            tm0 = fmaxf(tm0, __shfl_xor_sync(0xffffffffu, tm0, 2));
            tm1 = fmaxf(tm1, __shfl_xor_sync(0xffffffffu, tm1, 1));
            tm1 = fmaxf(tm1, __shfl_xor_sync(0xffffffffu, tm1, 2));
            float mn0 = fmaxf(m0, tm0), mn1 = fmaxf(m1, tm1);
            float ls0 = 0.f, ls1 = 0.f;
#pragma unroll
            for (int ni = 0; ni < 8; ni++) {
                acc[ni][0] = __expf(acc[ni][0] - mn0);
                acc[ni][1] = __expf(acc[ni][1] - mn0);
                acc[ni][2] = __expf(acc[ni][2] - mn1);
                acc[ni][3] = __expf(acc[ni][3] - mn1);
                ls0 += acc[ni][0] + acc[ni][1];
                ls1 += acc[ni][2] + acc[ni][3];
            }
            ls0 += __shfl_xor_sync(0xffffffffu, ls0, 1);
            ls0 += __shfl_xor_sync(0xffffffffu, ls0, 2);
            ls1 += __shfl_xor_sync(0xffffffffu, ls1, 1);
            ls1 += __shfl_xor_sync(0xffffffffu, ls1, 2);
            l0 = l0 * __expf(m0 - mn0) + ls0; m0 = mn0;
            l1 = l1 * __expf(m1 - mn1) + ls1; m1 = mn1;

            // store e as fp32 pairs (precision-critical)
#pragma unroll
            for (int ni = 0; ni < 8; ni++) {
                *(float2*)&erow0[s0 + ni * 8 + j2] =
                    make_float2(acc[ni][0], acc[ni][1]);
                *(float2*)&erow1[s0 + ni * 8 + j2] =
                    make_float2(acc[ni][2], acc[ni][3]);
            }
            if (qd == 0) {
                g_mh[((size_t)(bh * TT + tg0)) * 32 + it] = mn0;
                g_mh[((size_t)(bh * TT + tg1)) * 32 + it] = mn1;
            }
        }

        __syncthreads();
        if (qd == 0) {
            mfin[r0] = m0; lfin[r0] = 1.0f / l0;
            mfin[r1] = m1; lfin[r1] = 1.0f / l1;
        }
        // issue vt tile 0
#pragma unroll
        for (int rep = 0; rep < 4; rep++) {
            int c = rep * 256 + tid;
            int arr = c >> 9, cc = c & 511, d = cc >> 3, j = cc & 7;
            const __half* src =
                (arr ? g_vtl : g_vth) + ((size_t)bh * DD + d) * TT + j * 8;
            cp16(smem_u32(stgA + arr * 4608 + d * 72 + j * 8), src);
        }
        CP_COMMIT();
        __syncthreads();

        // factors c_it = exp(mh - m_fin) / l into mh_s
#pragma unroll
        for (int i = 0; i < 8; i++) {
            int row = ty * 8 + i;
            float mf = mfin[row], il = lfin[row];
            for (int it2 = tx; it2 < ntiles; it2 += 16)
                mh_s[row][it2] =
                    __expf(g_mh[((size_t)(bh * TT + t0 + row)) * 32 + it2] - mf) * il;
        }

        // ---------------- Pass 2 ----------------
        float acc2[2][4][4];
#pragma unroll
        for (int mi = 0; mi < 2; mi++)
#pragma unroll
            for (int ni = 0; ni < 4; ni++)
#pragma unroll
                for (int r = 0; r < 4; r++) acc2[mi][ni][r] = 0.f;

        for (int it = 0; it < ntiles; it++) {
            const int s0 = it * 64;
            CP_WAIT(0);
            __syncthreads();
            if (it + 1 < ntiles) {
                __half* stn = ((it + 1) & 1) ? stgB : stgA;
#pragma unroll
                for (int rep = 0; rep < 4; rep++) {
                    int c = rep * 256 + tid;
                    int arr = c >> 9, cc = c & 511, d = cc >> 3, j = cc & 7;
                    const __half* src = (arr ? g_vtl : g_vth) +
                        ((size_t)bh * DD + d) * TT + s0 + 64 + j * 8;
                    cp16(smem_u32(stn + arr * 4608 + d * 72 + j * 8), src);
                }
                CP_COMMIT();
            }

            // sparsify + split a into f16 hi/lo
#pragma unroll
            for (int i = 0; i < 8; i++) {
                const int row = ty * 8 + i;
                const int t = t0 + row;
                const float fac = mh_s[row][it];
                const float* erow = g_e + ((size_t)(bh * TT + t)) * TT;
                float4 ev = *(const float4*)&erow[s0 + tx * 4];
                uint32_t word = g_mask[((size_t)(bh * TT + t)) * (TT / 32) +
                                       (s0 >> 5) + (tx >> 3)];
                int bp = (tx & 7) * 4;
                float a0 = ev.x * fac, a1 = ev.y * fac,
                      a2 = ev.z * fac, a3 = ev.w * fac;
                a0 = (a0 > 0.01f || ((word >> (bp + 0)) & 1u)) ? a0 : 0.f;
                a1 = (a1 > 0.01f || ((word >> (bp + 1)) & 1u)) ? a1 : 0.f;
                a2 = (a2 > 0.01f || ((word >> (bp + 2)) & 1u)) ? a2 : 0.f;
                a3 = (a3 > 0.01f || ((word >> (bp + 3)) & 1u)) ? a3 : 0.f;
                __half h0, lo0, h1, lo1, h2, lo2, h3, lo3;
                split2(a0, h0, lo0); split2(a1, h1, lo1);
                split2(a2, h2, lo2); split2(a3, h3, lo3);
                uint32_t idx = row * 36 + tx * 2;
                ((uint32_t*)a_smh)[idx]     = pk(h0, h1);
                ((uint32_t*)a_smh)[idx + 1] = pk(h2, h3);
                ((uint32_t*)a_sml)[idx]     = pk(lo0, lo1);
                ((uint32_t*)a_sml)[idx + 1] = pk(lo2, lo3);
            }
            __syncthreads();

            const uint32_t* ah32 = (const uint32_t*)a_smh;
            const uint32_t* al32 = (const uint32_t*)a_sml;
            const uint32_t* vh32 =
                (const uint32_t*)((it & 1) ? stgB : stgA);
            const uint32_t* vl32 = vh32 + 2304;
#pragma unroll
            for (int ks = 0; ks < 4; ks++) {
                uint32_t ah[2][4], al[2][4], bh[4][2], bl[4][2];
#pragma unroll
                for (int mi = 0; mi < 2; mi++) {
                    int base = (wm * 32 + mi * 16 + g) * 36 + ks * 8 + qd;
                    ah[mi][0] = ah32[base];
                    ah[mi][1] = ah32[base + 8 * 36];
                    ah[mi][2] = ah32[base + 4];
                    ah[mi][3] = ah32[base + 8 * 36 + 4];
                    al[mi][0] = al32[base];
                    al[mi][1] = al32[base + 8 * 36];
                    al[mi][2] = al32[base + 4];
                    al[mi][3] = al32[base + 8 * 36 + 4];
                }
#pragma unroll
                for (int ni = 0; ni < 4; ni++) {
                    int base = (wn * 32 + ni * 8 + g) * 36 + ks * 8 + qd;
                    bh[ni][0] = vh32[base];
                    bh[ni][1] = vh32[base + 4];
                    bl[ni][0] = vl32[base];
                    bl[ni][1] = vl32[base + 4];
                }
#pragma unroll
                for (int mi = 0; mi < 2; mi++)
#pragma unroll
                    for (int ni = 0; ni < 4; ni++) {
                        mma16816(acc2[mi][ni], ah[mi], bh[ni]);
                        mma16816(acc2[mi][ni], ah[mi], bl[ni]);
                        mma16816(acc2[mi][ni], al[mi], bh[ni]);
                    }
            }
        }

        // epilogue: split output, write g_aoh/g_aol directly
        const int b = blockIdx.z, h = blockIdx.y;
#pragma unroll
        for (int mi = 0; mi < 2; mi++) {
#pragma unroll
            for (int ni = 0; ni < 4; ni++) {
                int mrow = wm * 32 + mi * 16 + g;
                int n = wn * 32 + ni * 8 + j2;
#pragma unroll
                for (int rr = 0; rr < 2; rr++) {
                    int t = t0 + mrow + rr * 8;
                    float v0 = acc2[mi][ni][rr * 2 + 0];
                    float v1 = acc2[mi][ni][rr * 2 + 1];
                    __half h0, lo0, h1, lo1;
                    split2(v0, h0, lo0);
                    split2(v1, h1, lo1);
                    size_t o = ((size_t)(b * TT + t) * CC + h * 64 + n) >> 1;
                    ((uint32_t*)g_aoh)[o] = pk(h0, h1);
                    ((uint32_t*)g_aol)[o] = pk(lo0, lo1);
                }
            }
        }
        __syncthreads();
    }
}

// ---------------------------------------------------------------------------
extern "C" void kernel_launch(void* const* d_in, const int* in_sizes, int n_in,
                              void* d_out, int out_size) {
    const float* x    = (const float*)d_in[0];
    const float* Wqkv = (const float*)d_in[1];
    const float* bqkv = (const float*)d_in[2];
    const float* Wout = (const float*)d_in[3];
    const float* bout = (const float*)d_in[4];
    float* out = (float*)d_out;

    cudaFuncSetAttribute(attn_kernel,
                         cudaFuncAttributeMaxDynamicSharedMemorySize, ATTN_SMEM);
    cudaFuncSetAttribute(hmma_gemm,
                         cudaFuncAttributeMaxDynamicSharedMemorySize, GEMM_SMEM);

    // 0) Regrow bitmask (input-independent)
    mask_kernel<<<dim3(4, TT, BB * HH), 256>>>();

    // 1) Split-f16 conversions
    conv_rows<<<(BB * TT * CC / 4 + 255) / 256, 256>>>(x, BB * TT * CC / 4);
    conv_tr<<<dim3(3 * CC / 32, CC / 32), dim3(32, 8)>>>(Wqkv, CC, 3 * CC, 0);
    conv_tr<<<dim3(CC / 32, CC / 32), dim3(32, 8)>>>(Wout, CC, CC, 1);

    // 2) QKV projection -> q,k (2-way f16), v (fp32)
    hmma_gemm<<<dim3(3 * CC / 128, BB * TT / 128), 256, GEMM_SMEM>>>(
        bqkv, nullptr, 0);

    // 2b) V -> V^T f16 hi/lo
    vt_split<<<dim3(DD / 32, TT / 32, BB * HH), dim3(32, 8)>>>();

    // 3) Attention (pass1 HMMA QK + fragment softmax, pass2 HMMA AV)
    attn_kernel<<<dim3(TT / 256, HH, BB), 256, ATTN_SMEM>>>();

    // 4) Output projection
    hmma_gemm<<<dim3(CC / 128, BB * TT / 128), 256, GEMM_SMEM>>>(
        bout, out, 1);
}